// round 8
// baseline (speedup 1.0000x reference)
#include <cuda_runtime.h>
#include <cuda_bf16.h>
#include <stdint.h>

#define T_SEQ 2560
#define HID   7168
#define QLRD  1536
#define NH    64
#define HD    128
#define NQ    8192
#define TQ    512
#define TB    2048
#define KSPLIT 8
#define KCHUNK (HID / KSPLIT)
#define NEGBIG (-1000000000.0f)

// ------------------- device scratch -------------------
__device__ __align__(16) float g_kpart[KSPLIT * T_SEQ * HD];
__device__ __align__(16) float g_q[TQ * NQ];
__device__ __align__(16) float g_w[TQ * NH];
__device__ __align__(16) float g_score[TQ * T_SEQ];
// bf16 3-way splits of q (post-rope) and k (post-LN/rope)
__device__ __align__(16) __nv_bfloat16 g_qs0[TQ * NQ];
__device__ __align__(16) __nv_bfloat16 g_qs1[TQ * NQ];
__device__ __align__(16) __nv_bfloat16 g_qs2[TQ * NQ];
__device__ __align__(16) __nv_bfloat16 g_ks0[T_SEQ * HD];
__device__ __align__(16) __nv_bfloat16 g_ks1[T_SEQ * HD];
__device__ __align__(16) __nv_bfloat16 g_ks2[T_SEQ * HD];
// bf16 3-way splits of qr (active rows) and wq_b transposed [NQ][QLRD]
__device__ __align__(16) __nv_bfloat16 g_qrs0[TQ * QLRD];
__device__ __align__(16) __nv_bfloat16 g_qrs1[TQ * QLRD];
__device__ __align__(16) __nv_bfloat16 g_qrs2[TQ * QLRD];
__device__ __align__(16) __nv_bfloat16 g_wqT0[NQ * QLRD];
__device__ __align__(16) __nv_bfloat16 g_wqT1[NQ * QLRD];
__device__ __align__(16) __nv_bfloat16 g_wqT2[NQ * QLRD];

// ------------------- mma.sync / cp.async helpers (baseline PTX) -------------------
__device__ __forceinline__ void ldsm4(uint32_t* r, uint32_t addr) {
    asm volatile("ldmatrix.sync.aligned.m8n8.x4.shared.b16 {%0,%1,%2,%3},[%4];"
        : "=r"(r[0]), "=r"(r[1]), "=r"(r[2]), "=r"(r[3]) : "r"(addr));
}
__device__ __forceinline__ void mma16816(float* d, const uint32_t* a, const uint32_t* b) {
    asm volatile("mma.sync.aligned.m16n8k16.row.col.f32.bf16.bf16.f32 "
        "{%0,%1,%2,%3},{%4,%5,%6,%7},{%8,%9},{%0,%1,%2,%3};"
        : "+f"(d[0]), "+f"(d[1]), "+f"(d[2]), "+f"(d[3])
        : "r"(a[0]), "r"(a[1]), "r"(a[2]), "r"(a[3]), "r"(b[0]), "r"(b[1]));
}
__device__ __forceinline__ void cpa16(uint32_t dst, const void* src) {
    asm volatile("cp.async.cg.shared.global [%0],[%1],16;" :: "r"(dst), "l"(src));
}
#define CP_COMMIT() asm volatile("cp.async.commit_group;" ::: "memory")
#define CP_WAIT0()  asm volatile("cp.async.wait_group 0;" ::: "memory")

__constant__ int c_aidx[6] = {0, 0, 1, 1, 0, 2};
__constant__ int c_bidx[6] = {0, 1, 0, 1, 2, 0};

// ------------------- score: pipelined HMMA bf16 3-split/6-product + fused epilogue -----
#define LDT 40
#define TILE_B (128 * LDT * 2)

__global__ __launch_bounds__(256, 2) void score_mma()
{
    __shared__ __nv_bfloat16 sT[2][2][128 * LDT];
    __shared__ float part[8][64];

    const int bs = blockIdx.x, bt = blockIdx.y;
    if (bs * 128 > TB + 2 * bt + 1) return;   // causal skip

    const int tid = threadIdx.x, l = tid & 31, wid = tid >> 5;
    const int wm = wid & 3, wn = wid >> 2;

    const __nv_bfloat16* qa[3] = {g_qs0, g_qs1, g_qs2};
    const __nv_bfloat16* kb[3] = {g_ks0, g_ks1, g_ks2};

    float acc[2][8][4] = {};

    const uint32_t sbase = (uint32_t)__cvta_generic_to_shared(&sT[0][0][0]);
    const int r0 = (tid + 0) >> 2,   g0 = (tid + 0) & 3;
    const int r1 = (tid + 256) >> 2, g1 = (tid + 256) & 3;

    uint32_t aOff[2], bOff[4];
#pragma unroll
    for (int mi = 0; mi < 2; mi++)
        aOff[mi] = ((wm * 32 + mi * 16 + (l & 15)) * LDT + (l >> 4) * 8) * 2;
#pragma unroll
    for (int nj = 0; nj < 4; nj++)
        bOff[nj] = ((wn * 64 + nj * 16 + ((l >> 4) * 8) + (l & 7)) * LDT + ((l >> 3) & 1) * 8) * 2;

    auto issue_stage = [&](int s, int buf) {
        const int p = s >> 2, kc = s & 3;
        const __nv_bfloat16* asrc = qa[c_aidx[p]] + (size_t)bt * 128 * HD + kc * 32;
        const __nv_bfloat16* bsrc = kb[c_bidx[p]] + (size_t)bs * 128 * HD + kc * 32;
        const uint32_t ab = sbase + buf * 2 * TILE_B;
        const uint32_t bb = ab + TILE_B;
        cpa16(ab + (r0 * LDT + g0 * 8) * 2, asrc + (size_t)r0 * HD + g0 * 8);
        cpa16(ab + (r1 * LDT + g1 * 8) * 2, asrc + (size_t)r1 * HD + g1 * 8);
        cpa16(bb + (r0 * LDT + g0 * 8) * 2, bsrc + (size_t)r0 * HD + g0 * 8);
        cpa16(bb + (r1 * LDT + g1 * 8) * 2, bsrc + (size_t)r1 * HD + g1 * 8);
        CP_COMMIT();
    };

    issue_stage(0, 0);
#pragma unroll 1
    for (int s = 0; s < 24; s++) {
        const int buf = s & 1;
        CP_WAIT0();
        __syncthreads();
        if (s + 1 < 24) issue_stage(s + 1, buf ^ 1);
        const uint32_t ab = sbase + buf * 2 * TILE_B;
        const uint32_t bb = ab + TILE_B;
#pragma unroll
        for (int ks = 0; ks < 2; ks++) {
            uint32_t af[2][4], bf[4][4];
            ldsm4(af[0], ab + aOff[0] + ks * 32);
            ldsm4(af[1], ab + aOff[1] + ks * 32);
#pragma unroll
            for (int nj = 0; nj < 4; nj++) ldsm4(bf[nj], bb + bOff[nj] + ks * 32);
#pragma unroll
            for (int mi = 0; mi < 2; mi++)
#pragma unroll
                for (int ni = 0; ni < 8; ni++)
                    mma16816(acc[mi][ni], af[mi], &bf[ni >> 1][(ni & 1) * 2]);
        }
    }

    const int rbase = wm * 32 + (l >> 2);
    const float w0 = g_w[bt * 128 + rbase];
    const float w1 = g_w[bt * 128 + rbase + 8];
    const float w2 = g_w[bt * 128 + rbase + 16];
    const float w3 = g_w[bt * 128 + rbase + 24];
#pragma unroll
    for (int ni = 0; ni < 8; ni++) {
        float s0 = fmaxf(acc[0][ni][0], 0.0f) * w0 + fmaxf(acc[0][ni][2], 0.0f) * w1
                 + fmaxf(acc[1][ni][0], 0.0f) * w2 + fmaxf(acc[1][ni][2], 0.0f) * w3;
        float s1 = fmaxf(acc[0][ni][1], 0.0f) * w0 + fmaxf(acc[0][ni][3], 0.0f) * w1
                 + fmaxf(acc[1][ni][1], 0.0f) * w2 + fmaxf(acc[1][ni][3], 0.0f) * w3;
#pragma unroll
        for (int o = 4; o < 32; o <<= 1) {
            s0 += __shfl_xor_sync(0xffffffffu, s0, o);
            s1 += __shfl_xor_sync(0xffffffffu, s1, o);
        }
        if (l < 4) {
            part[wid][ni * 8 + 2 * l] = s0;
            part[wid][ni * 8 + 2 * l + 1] = s1;
        }
    }
    __syncthreads();
    {
        const int col = tid & 127, tt = tid >> 7;
        const int wa = (col >> 6) * 4 + tt * 2;
        float s = part[wa][col & 63] + part[wa + 1][col & 63];
        g_score[(size_t)(bt * 2 + tt) * T_SEQ + bs * 128 + col] = s;
    }
}

// ------------------- q = qr @ wq_b via pipelined HMMA 6-product, 64x64 tiles ------------
// grid (128 n-tiles, 8 m-tiles) = 1024 blocks, 256 threads, warp grid 2m x 4n
#define QLDT 40
#define QTILE_B (64 * QLDT * 2)   // 5120 bytes per 64x32 tile

__global__ __launch_bounds__(256, 3) void q_mma()
{
    __shared__ __nv_bfloat16 sT[2][2][64 * QLDT];

    const int bn = blockIdx.x, bm = blockIdx.y;
    const int tid = threadIdx.x, l = tid & 31, wid = tid >> 5;
    const int wm = wid & 1, wn = wid >> 1;

    const __nv_bfloat16* qa[3] = {g_qrs0, g_qrs1, g_qrs2};
    const __nv_bfloat16* wb[3] = {g_wqT0, g_wqT1, g_wqT2};

    float acc[2][2][4] = {};

    const uint32_t sbase = (uint32_t)__cvta_generic_to_shared(&sT[0][0][0]);
    const int r0 = tid >> 2, g0 = tid & 3;   // 256 chunks per 64x32 tile, 1 A + 1 B per thread

    uint32_t aOff[2], bOff;
#pragma unroll
    for (int mi = 0; mi < 2; mi++)
        aOff[mi] = ((wm * 32 + mi * 16 + (l & 15)) * QLDT + (l >> 4) * 8) * 2;
    bOff = ((wn * 16 + ((l >> 4) * 8) + (l & 7)) * QLDT + ((l >> 3) & 1) * 8) * 2;

    auto issue_stage = [&](int s, int buf) {
        const int p = s / 48, kc = s % 48;
        const __nv_bfloat16* asrc = qa[c_aidx[p]] + (size_t)(bm * 64 + r0) * QLRD + kc * 32 + g0 * 8;
        const __nv_bfloat16* bsrc = wb[c_bidx[p]] + (size_t)(bn * 64 + r0) * QLRD + kc * 32 + g0 * 8;
        const uint32_t ab = sbase + buf * 2 * QTILE_B;
        const uint32_t bb = ab + QTILE_B;
        cpa16(ab + (r0 * QLDT + g0 * 8) * 2, asrc);
        cpa16(bb + (r0 * QLDT + g0 * 8) * 2, bsrc);
        CP_COMMIT();
    };

    issue_stage(0, 0);
#pragma unroll 1
    for (int s = 0; s < 288; s++) {
        const int buf = s & 1;
        CP_WAIT0();
        __syncthreads();
        if (s + 1 < 288) issue_stage(s + 1, buf ^ 1);
        const uint32_t ab = sbase + buf * 2 * QTILE_B;
        const uint32_t bb = ab + QTILE_B;
#pragma unroll
        for (int ks = 0; ks < 2; ks++) {
            uint32_t af[2][4], bf[4];
            ldsm4(af[0], ab + aOff[0] + ks * 32);
            ldsm4(af[1], ab + aOff[1] + ks * 32);
            ldsm4(bf, bb + bOff + ks * 32);
#pragma unroll
            for (int mi = 0; mi < 2; mi++)
#pragma unroll
                for (int ni = 0; ni < 2; ni++)
                    mma16816(acc[mi][ni], af[mi], &bf[ni * 2]);
        }
    }

    const int rb = bm * 64 + wm * 32 + (l >> 2);
    const int cb = bn * 64 + wn * 16 + 2 * (l & 3);
#pragma unroll
    for (int mi = 0; mi < 2; mi++)
#pragma unroll
        for (int ni = 0; ni < 2; ni++) {
            const int row = rb + mi * 16, col = cb + ni * 8;
            *(float2*)&g_q[(size_t)row * NQ + col]       = make_float2(acc[mi][ni][0], acc[mi][ni][1]);
            *(float2*)&g_q[(size_t)(row + 8) * NQ + col] = make_float2(acc[mi][ni][2], acc[mi][ni][3]);
        }
}

// ------------------- fp32 SGEMM for k = x @ wk_w (split-K partials) -------------------
__global__ __launch_bounds__(256) void sgemm_k(
    const float* __restrict__ A, const float* __restrict__ B)
{
    __shared__ float As[8][132];
    __shared__ float Bs[8][132];

    const int tid = threadIdx.x;
    const int tx = tid & 15, ty = tid >> 4;
    const float* Ab = A + (size_t)blockIdx.x * 128 * HID;
    float* Cb = g_kpart + (size_t)blockIdx.z * T_SEQ * HD + (size_t)blockIdx.x * 128 * HD;

    const int arow = tid >> 1, aoff = (tid & 1) * 4;
    const int bkk = tid >> 5, bcol = (tid & 31) * 4;

    float acc[8][8];
#pragma unroll
    for (int i = 0; i < 8; i++)
#pragma unroll
        for (int j = 0; j < 8; j++) acc[i][j] = 0.0f;

    int k0 = blockIdx.z * KCHUNK;
    const int kend = k0 + KCHUNK;
    for (; k0 < kend; k0 += 8) {
        float4 av = *(const float4*)(Ab + (size_t)arow * HID + k0 + aoff);
        float4 bv = *(const float4*)(B + (size_t)(k0 + bkk) * HD + bcol);
        As[aoff + 0][arow] = av.x; As[aoff + 1][arow] = av.y;
        As[aoff + 2][arow] = av.z; As[aoff + 3][arow] = av.w;
        *(float4*)&Bs[bkk][bcol] = bv;
        __syncthreads();
#pragma unroll
        for (int kk = 0; kk < 8; kk++) {
            float4 a0 = *(const float4*)&As[kk][ty * 8];
            float4 a1 = *(const float4*)&As[kk][ty * 8 + 4];
            float4 b0 = *(const float4*)&Bs[kk][tx * 8];
            float4 b1 = *(const float4*)&Bs[kk][tx * 8 + 4];
            float a[8] = {a0.x, a0.y, a0.z, a0.w, a1.x, a1.y, a1.z, a1.w};
            float b[8] = {b0.x, b0.y, b0.z, b0.w, b1.x, b1.y, b1.z, b1.w};
#pragma unroll
            for (int i = 0; i < 8; i++)
#pragma unroll
                for (int j = 0; j < 8; j++)
                    acc[i][j] = fmaf(a[i], b[j], acc[i][j]);
        }
        __syncthreads();
    }
#pragma unroll
    for (int i = 0; i < 8; i++) {
        float* cr = Cb + (size_t)(ty * 8 + i) * HD + tx * 8;
        *(float4*)cr       = make_float4(acc[i][0], acc[i][1], acc[i][2], acc[i][3]);
        *(float4*)(cr + 4) = make_float4(acc[i][4], acc[i][5], acc[i][6], acc[i][7]);
    }
}

// ------------------- split-K reduce + LayerNorm + RoPE + bf16x3 split for k -------------
__global__ __launch_bounds__(128) void k_postproc(
    const float* __restrict__ gamma, const float* __restrict__ beta,
    const float* __restrict__ fcos, const float* __restrict__ fsin)
{
    const int t = blockIdx.x;
    const int d = threadIdx.x;
    float v = 0.0f;
#pragma unroll
    for (int p = 0; p < KSPLIT; p++)
        v += g_kpart[(size_t)p * T_SEQ * HD + (size_t)t * HD + d];

    __shared__ float red[128];
    __shared__ float buf[128];
    red[d] = v; __syncthreads();
#pragma unroll
    for (int s = 64; s > 0; s >>= 1) { if (d < s) red[d] += red[d + s]; __syncthreads(); }
    const float mu = red[0] * (1.0f / 128.0f);
    __syncthreads();
    const float diff = v - mu;
    red[d] = diff * diff; __syncthreads();
#pragma unroll
    for (int s = 64; s > 0; s >>= 1) { if (d < s) red[d] += red[d + s]; __syncthreads(); }
    const float var = red[0] * (1.0f / 128.0f);
    const float inv = __frsqrt_rn(var + 1e-6f);
    const float nrm = diff * inv * gamma[d] + beta[d];
    buf[d] = nrm; __syncthreads();

    float outv;
    if (d < 32) {
        float c = fcos[t * 32 + d], s = fsin[t * 32 + d];
        outv = buf[d] * c - buf[d + 32] * s;
    } else if (d < 64) {
        float c = fcos[t * 32 + d - 32], s = fsin[t * 32 + d - 32];
        outv = buf[d - 32] * s + buf[d] * c;
    } else {
        outv = nrm;
    }
    __nv_bfloat16 b0 = __float2bfloat16(outv);
    float r1 = outv - __bfloat162float(b0);
    __nv_bfloat16 b1 = __float2bfloat16(r1);
    float r2 = r1 - __bfloat162float(b1);
    const size_t o = (size_t)t * HD + d;
    g_ks0[o] = b0; g_ks1[o] = b1; g_ks2[o] = __float2bfloat16(r2);
}

// ------------------- RoPE on q (fp32, in place) -------------------
__global__ void q_rope(const float* __restrict__ fcos, const float* __restrict__ fsin)
{
    int idx = blockIdx.x * blockDim.x + threadIdx.x;
    if (idx >= TQ * NH * 32) return;
    int i = idx & 31;
    int h = (idx >> 5) & 63;
    int tq = idx >> 11;
    int t = TB + tq;
    float c = fcos[t * 32 + i], s = fsin[t * 32 + i];
    float* q = g_q + (size_t)tq * NQ + h * HD;
    float x1 = q[i], x2 = q[i + 32];
    q[i]      = x1 * c - x2 * s;
    q[i + 32] = x1 * s + x2 * c;
}

// ------------------- bf16x3 split of q (post-rope) -------------------
__global__ void q_split()
{
    int i = blockIdx.x * blockDim.x + threadIdx.x;
    if (i >= TQ * NQ) return;
    float v = g_q[i];
    __nv_bfloat16 b0 = __float2bfloat16(v);
    float r1 = v - __bfloat162float(b0);
    __nv_bfloat16 b1 = __float2bfloat16(r1);
    float r2 = r1 - __bfloat162float(b1);
    g_qs0[i] = b0; g_qs1[i] = b1; g_qs2[i] = __float2bfloat16(r2);
}

// ------------------- bf16x3 split of qr active rows -------------------
__global__ void qr_split(const float* __restrict__ qr)
{
    int i = blockIdx.x * blockDim.x + threadIdx.x;
    if (i >= TQ * QLRD) return;
    float v = qr[(size_t)TB * QLRD + i];
    __nv_bfloat16 b0 = __float2bfloat16(v);
    float r1 = v - __bfloat162float(b0);
    __nv_bfloat16 b1 = __float2bfloat16(r1);
    float r2 = r1 - __bfloat162float(b1);
    g_qrs0[i] = b0; g_qrs1[i] = b1; g_qrs2[i] = __float2bfloat16(r2);
}

// ------------------- transpose + bf16x3 split of wq_b -> [NQ][QLRD] -------------------
__global__ __launch_bounds__(256) void wq_tsplit(const float* __restrict__ wq_b)
{
    __shared__ float t[32][33];
    const int bx = blockIdx.x;  // n/32
    const int by = blockIdx.y;  // k/32
    const int tx = threadIdx.x & 31, ty = threadIdx.x >> 5;
#pragma unroll
    for (int i = 0; i < 4; i++) {
        int k = by * 32 + ty + i * 8;
        t[ty + i * 8][tx] = wq_b[(size_t)k * NQ + bx * 32 + tx];
    }
    __syncthreads();
#pragma unroll
    for (int i = 0; i < 4; i++) {
        int n = bx * 32 + ty + i * 8;
        float v = t[tx][ty + i * 8];
        __nv_bfloat16 b0 = __float2bfloat16(v);
        float r1 = v - __bfloat162float(b0);
        __nv_bfloat16 b1 = __float2bfloat16(r1);
        float r2 = r1 - __bfloat162float(b1);
        size_t o = (size_t)n * QLRD + by * 32 + tx;
        g_wqT0[o] = b0; g_wqT1[o] = b1; g_wqT2[o] = __float2bfloat16(r2);
    }
}

// ------------------- weights for active rows -------------------
__global__ __launch_bounds__(256) void w_gemv(const float* __restrict__ x, const float* __restrict__ wproj)
{
    const int tq = blockIdx.x;
    const int tid = threadIdx.x;
    const int h = tid & 63;
    const int kg = tid >> 6;
    const float* xr = x + (size_t)(TB + tq) * HID + (size_t)kg * (HID / 4);
    const float* wp = wproj + (size_t)kg * (HID / 4) * NH + h;
    float acc = 0.0f;
    for (int k = 0; k < HID / 4; k += 4) {
        float4 xv = *(const float4*)(xr + k);
        acc = fmaf(xv.x, wp[(k + 0) * NH], acc);
        acc = fmaf(xv.y, wp[(k + 1) * NH], acc);
        acc = fmaf(xv.z, wp[(k + 2) * NH], acc);
        acc = fmaf(xv.w, wp[(k + 3) * NH], acc);
    }
    __shared__ float red[4][64];
    red[kg][h] = acc; __syncthreads();
    if (tid < 64) {
        float s = red[0][tid] + red[1][tid] + red[2][tid] + red[3][tid];
        s = (s * 0.125f) * 0.08838834764831843f;
        g_w[tq * NH + tid] = s;
    }
}

// ------------------- fixed fill for rows t < 2048 -------------------
__global__ void fill_fixed(float* __restrict__ out)
{
    size_t i = (size_t)blockIdx.x * blockDim.x + threadIdx.x;
    const size_t total = (size_t)TB * T_SEQ / 4;
    if (i >= total) return;
    size_t s4 = (i % (T_SEQ / 4)) * 4;
    float v = (s4 < TB) ? 0.0f : NEGBIG;
    ((float4*)out)[i] = make_float4(v, v, v, v);
}

// ------------------- exact top-2048 via radix select -------------------
__global__ __launch_bounds__(256) void topk_select(float* __restrict__ out)
{
    __shared__ unsigned keys[T_SEQ];
    __shared__ unsigned char flags[T_SEQ];
    __shared__ int redc[9];
    __shared__ int rlt[8], req[8];
    __shared__ int cnts[256];

    const int tq = blockIdx.x;
    const int t = TB + tq;
    const int n = t + 1;
    const int tid = threadIdx.x;
    const int lane = tid & 31, wid = tid >> 5;
    const float* srow = g_score + (size_t)tq * T_SEQ;

    for (int i = tid; i < n; i += 256) {
        unsigned b = __float_as_uint(srow[i]);
        keys[i] = b ^ ((b & 0x80000000u) ? 0xFFFFFFFFu : 0x80000000u);
    }
    __syncthreads();

    const int m0 = tq + 1;
    int m = m0;
    unsigned prefix = 0;
    for (int bit = 31; bit >= 0; bit--) {
        const unsigned pshift = prefix >> bit;
        int c = 0;
        for (int i = tid; i < n; i += 256)
            c += ((keys[i] >> bit) == pshift);
#pragma unroll
        for (int o = 16; o; o >>= 1) c += __shfl_xor_sync(0xffffffffu, c, o);
        if (lane == 0) redc[wid] = c;
        __syncthreads();
        if (tid == 0) {
            int tot = 0;
            for (int w = 0; w < 8; w++) tot += redc[w];
            redc[8] = tot;
        }
        __syncthreads();
        const int cnt = redc[8];
        if (m > cnt) { m -= cnt; prefix |= (1u << bit); }
        __syncthreads();
    }
    const unsigned theta = prefix;

    int clt = 0, ceq = 0;
    for (int i = tid; i < n; i += 256) {
        unsigned k = keys[i];
        clt += (k < theta);
        ceq += (k == theta);
    }
#pragma unroll
    for (int o = 16; o; o >>= 1) {
        clt += __shfl_xor_sync(0xffffffffu, clt, o);
        ceq += __shfl_xor_sync(0xffffffffu, ceq, o);
    }
    if (lane == 0) { rlt[wid] = clt; req[wid] = ceq; }
    __syncthreads();
    int count_lt = 0, count_eq = 0;
    for (int w = 0; w < 8; w++) { count_lt += rlt[w]; count_eq += req[w]; }
    const int keep_eq = count_eq - (m0 - count_lt);

    const int chunk = (n + 255) / 256;
    const int beg = tid * chunk;
    const int end = (beg + chunk < n) ? (beg + chunk) : n;
    int local = 0;
    for (int i = beg; i < end; i++) local += (keys[i] == theta);
    cnts[tid] = local;
    __syncthreads();
    if (tid == 0) {
        int run = 0;
        for (int i = 0; i < 256; i++) { int c = cnts[i]; cnts[i] = run; run += c; }
    }
    __syncthreads();
    int rank = cnts[tid];
    for (int i = beg; i < end; i++)
        if (keys[i] == theta) { flags[i] = (rank < keep_eq) ? 1 : 0; rank++; }
    __syncthreads();

    float* orow = out + (size_t)t * T_SEQ;
    for (int s = tid; s < T_SEQ; s += 256) {
        float v = NEGBIG;
        if (s < n) {
            unsigned k = keys[s];
            if (k > theta || (k == theta && flags[s])) v = 0.0f;
        }
        orow[s] = v;
    }
}

// ------------------- launch -------------------
extern "C" void kernel_launch(void* const* d_in, const int* in_sizes, int n_in,
                              void* d_out, int out_size)
{
    (void)in_sizes; (void)n_in; (void)out_size;
    const float* x     = (const float*)d_in[0];
    const float* qr    = (const float*)d_in[1];
    const float* fcos  = (const float*)d_in[2];
    const float* fsin  = (const float*)d_in[3];
    const float* wq_b  = (const float*)d_in[5];
    const float* wk_w  = (const float*)d_in[6];
    const float* kgam  = (const float*)d_in[7];
    const float* kbet  = (const float*)d_in[8];
    const float* wproj = (const float*)d_in[9];
    float* out = (float*)d_out;

    sgemm_k<<<dim3(20, 1, KSPLIT), 256>>>(x, wk_w);
    k_postproc<<<T_SEQ, 128>>>(kgam, kbet, fcos, fsin);
    w_gemv<<<TQ, 256>>>(x, wproj);
    qr_split<<<(TQ * QLRD + 255) / 256, 256>>>(qr);
    wq_tsplit<<<dim3(NQ / 32, QLRD / 32), 256>>>(wq_b);
    q_mma<<<dim3(NQ / 64, TQ / 64), 256>>>();
    q_rope<<<(TQ * NH * 32 + 255) / 256, 256>>>(fcos, fsin);
    q_split<<<(TQ * NQ + 255) / 256, 256>>>();
    score_mma<<<dim3(T_SEQ / 128, 256), 256>>>();
    fill_fixed<<<((TB * T_SEQ / 4) + 255) / 256, 256>>>(out);
    topk_select<<<TQ, 256>>>(out);
}

// round 9
// speedup vs baseline: 1.5583x; 1.5583x over previous
#include <cuda_runtime.h>
#include <cuda_fp16.h>
#include <stdint.h>

#define T_SEQ 2560
#define HID   7168
#define QLRD  1536
#define NH    64
#define HD    128
#define NQ    8192
#define TQ    512
#define TB    2048
#define KSPLIT 8
#define KCHUNK (HID / KSPLIT)
#define NEGBIG (-1000000000.0f)

// ------------------- device scratch -------------------
__device__ __align__(16) float g_kpart[KSPLIT * T_SEQ * HD];
__device__ __align__(16) float g_q[TQ * NQ];
__device__ __align__(16) float g_w[TQ * NH];
__device__ __align__(16) float g_score[TQ * T_SEQ];
// fp16 2-way splits
__device__ __align__(16) __half g_qs0[TQ * NQ];
__device__ __align__(16) __half g_qs1[TQ * NQ];
__device__ __align__(16) __half g_ks0[T_SEQ * HD];
__device__ __align__(16) __half g_ks1[T_SEQ * HD];
__device__ __align__(16) __half g_qrs0[TQ * QLRD];
__device__ __align__(16) __half g_qrs1[TQ * QLRD];
__device__ __align__(16) __half g_wqT0[NQ * QLRD];
__device__ __align__(16) __half g_wqT1[NQ * QLRD];

// ------------------- mma.sync / cp.async helpers (baseline PTX) -------------------
__device__ __forceinline__ void ldsm4(uint32_t* r, uint32_t addr) {
    asm volatile("ldmatrix.sync.aligned.m8n8.x4.shared.b16 {%0,%1,%2,%3},[%4];"
        : "=r"(r[0]), "=r"(r[1]), "=r"(r[2]), "=r"(r[3]) : "r"(addr));
}
__device__ __forceinline__ void mma16816(float* d, const uint32_t* a, const uint32_t* b) {
    asm volatile("mma.sync.aligned.m16n8k16.row.col.f32.f16.f16.f32 "
        "{%0,%1,%2,%3},{%4,%5,%6,%7},{%8,%9},{%0,%1,%2,%3};"
        : "+f"(d[0]), "+f"(d[1]), "+f"(d[2]), "+f"(d[3])
        : "r"(a[0]), "r"(a[1]), "r"(a[2]), "r"(a[3]), "r"(b[0]), "r"(b[1]));
}
__device__ __forceinline__ void cpa16(uint32_t dst, const void* src) {
    asm volatile("cp.async.cg.shared.global [%0],[%1],16;" :: "r"(dst), "l"(src));
}
#define CP_COMMIT() asm volatile("cp.async.commit_group;" ::: "memory")
#define CP_WAIT0()  asm volatile("cp.async.wait_group 0;" ::: "memory")

__constant__ int c_aidx[3] = {0, 0, 1};
__constant__ int c_bidx[3] = {0, 1, 0};

#define LDT 40
#define TILE_B (128 * LDT * 2)

// ------------------- score: pipelined HMMA fp16 2-split/3-product + fused epilogue -----
// grid (20 s-tiles, 256 t-pair tiles), 256 threads. 12 stages of K=32
__global__ __launch_bounds__(256, 2) void score_mma()
{
    __shared__ __half sT[2][2][128 * LDT];
    __shared__ float part[8][64];

    const int bs = blockIdx.x, bt = blockIdx.y;
    if (bs * 128 > TB + 2 * bt + 1) return;   // causal skip

    const int tid = threadIdx.x, l = tid & 31, wid = tid >> 5;
    const int wm = wid & 3, wn = wid >> 2;

    const __half* qa[2] = {g_qs0, g_qs1};
    const __half* kb[2] = {g_ks0, g_ks1};

    float acc[2][8][4] = {};

    const uint32_t sbase = (uint32_t)__cvta_generic_to_shared(&sT[0][0][0]);
    const int r0 = (tid + 0) >> 2,   g0 = (tid + 0) & 3;
    const int r1 = (tid + 256) >> 2, g1 = (tid + 256) & 3;

    uint32_t aOff[2], bOff[4];
#pragma unroll
    for (int mi = 0; mi < 2; mi++)
        aOff[mi] = ((wm * 32 + mi * 16 + (l & 15)) * LDT + (l >> 4) * 8) * 2;
#pragma unroll
    for (int nj = 0; nj < 4; nj++)
        bOff[nj] = ((wn * 64 + nj * 16 + ((l >> 4) * 8) + (l & 7)) * LDT + ((l >> 3) & 1) * 8) * 2;

    auto issue_stage = [&](int s, int buf) {
        const int p = s >> 2, kc = s & 3;
        const __half* asrc = qa[c_aidx[p]] + (size_t)bt * 128 * HD + kc * 32;
        const __half* bsrc = kb[c_bidx[p]] + (size_t)bs * 128 * HD + kc * 32;
        const uint32_t ab = sbase + buf * 2 * TILE_B;
        const uint32_t bb = ab + TILE_B;
        cpa16(ab + (r0 * LDT + g0 * 8) * 2, asrc + (size_t)r0 * HD + g0 * 8);
        cpa16(ab + (r1 * LDT + g1 * 8) * 2, asrc + (size_t)r1 * HD + g1 * 8);
        cpa16(bb + (r0 * LDT + g0 * 8) * 2, bsrc + (size_t)r0 * HD + g0 * 8);
        cpa16(bb + (r1 * LDT + g1 * 8) * 2, bsrc + (size_t)r1 * HD + g1 * 8);
        CP_COMMIT();
    };

    issue_stage(0, 0);
#pragma unroll 1
    for (int s = 0; s < 12; s++) {
        const int buf = s & 1;
        CP_WAIT0();
        __syncthreads();
        if (s + 1 < 12) issue_stage(s + 1, buf ^ 1);
        const uint32_t ab = sbase + buf * 2 * TILE_B;
        const uint32_t bb = ab + TILE_B;
#pragma unroll
        for (int ks = 0; ks < 2; ks++) {
            uint32_t af[2][4], bf[4][4];
            ldsm4(af[0], ab + aOff[0] + ks * 32);
            ldsm4(af[1], ab + aOff[1] + ks * 32);
#pragma unroll
            for (int nj = 0; nj < 4; nj++) ldsm4(bf[nj], bb + bOff[nj] + ks * 32);
#pragma unroll
            for (int mi = 0; mi < 2; mi++)
#pragma unroll
                for (int ni = 0; ni < 8; ni++)
                    mma16816(acc[mi][ni], af[mi], &bf[ni >> 1][(ni & 1) * 2]);
        }
    }

    const int rbase = wm * 32 + (l >> 2);
    const float w0 = g_w[bt * 128 + rbase];
    const float w1 = g_w[bt * 128 + rbase + 8];
    const float w2 = g_w[bt * 128 + rbase + 16];
    const float w3 = g_w[bt * 128 + rbase + 24];
#pragma unroll
    for (int ni = 0; ni < 8; ni++) {
        float s0 = fmaxf(acc[0][ni][0], 0.0f) * w0 + fmaxf(acc[0][ni][2], 0.0f) * w1
                 + fmaxf(acc[1][ni][0], 0.0f) * w2 + fmaxf(acc[1][ni][2], 0.0f) * w3;
        float s1 = fmaxf(acc[0][ni][1], 0.0f) * w0 + fmaxf(acc[0][ni][3], 0.0f) * w1
                 + fmaxf(acc[1][ni][1], 0.0f) * w2 + fmaxf(acc[1][ni][3], 0.0f) * w3;
#pragma unroll
        for (int o = 4; o < 32; o <<= 1) {
            s0 += __shfl_xor_sync(0xffffffffu, s0, o);
            s1 += __shfl_xor_sync(0xffffffffu, s1, o);
        }
        if (l < 4) {
            part[wid][ni * 8 + 2 * l] = s0;
            part[wid][ni * 8 + 2 * l + 1] = s1;
        }
    }
    __syncthreads();
    {
        const int col = tid & 127, tt = tid >> 7;
        const int wa = (col >> 6) * 4 + tt * 2;
        float s = part[wa][col & 63] + part[wa + 1][col & 63];
        g_score[(size_t)(bt * 2 + tt) * T_SEQ + bs * 128 + col] = s;
    }
}

// ------------------- q = qr @ wq_b: 128x128 clone of score_mma, 144 stages --------------
// grid (64 n-tiles, 4 m-tiles) = 256 blocks (single wave at occ 2)
__global__ __launch_bounds__(256, 2) void q_mma()
{
    __shared__ __half sT[2][2][128 * LDT];

    const int bn = blockIdx.x, bm = blockIdx.y;
    const int tid = threadIdx.x, l = tid & 31, wid = tid >> 5;
    const int wm = wid & 3, wn = wid >> 2;

    const __half* qa[2] = {g_qrs0, g_qrs1};
    const __half* wb[2] = {g_wqT0, g_wqT1};

    float acc[2][8][4] = {};

    const uint32_t sbase = (uint32_t)__cvta_generic_to_shared(&sT[0][0][0]);
    const int r0 = (tid + 0) >> 2,   g0 = (tid + 0) & 3;
    const int r1 = (tid + 256) >> 2, g1 = (tid + 256) & 3;

    uint32_t aOff[2], bOff[4];
#pragma unroll
    for (int mi = 0; mi < 2; mi++)
        aOff[mi] = ((wm * 32 + mi * 16 + (l & 15)) * LDT + (l >> 4) * 8) * 2;
#pragma unroll
    for (int nj = 0; nj < 4; nj++)
        bOff[nj] = ((wn * 64 + nj * 16 + ((l >> 4) * 8) + (l & 7)) * LDT + ((l >> 3) & 1) * 8) * 2;

    auto issue_stage = [&](int s, int buf) {
        const int p = s / 48, kc = s % 48;
        const __half* asrc = qa[c_aidx[p]] + (size_t)bm * 128 * QLRD + kc * 32;
        const __half* bsrc = wb[c_bidx[p]] + (size_t)bn * 128 * QLRD + kc * 32;
        const uint32_t ab = sbase + buf * 2 * TILE_B;
        const uint32_t bb = ab + TILE_B;
        cpa16(ab + (r0 * LDT + g0 * 8) * 2, asrc + (size_t)r0 * QLRD + g0 * 8);
        cpa16(ab + (r1 * LDT + g1 * 8) * 2, asrc + (size_t)r1 * QLRD + g1 * 8);
        cpa16(bb + (r0 * LDT + g0 * 8) * 2, bsrc + (size_t)r0 * QLRD + g0 * 8);
        cpa16(bb + (r1 * LDT + g1 * 8) * 2, bsrc + (size_t)r1 * QLRD + g1 * 8);
        CP_COMMIT();
    };

    issue_stage(0, 0);
#pragma unroll 1
    for (int s = 0; s < 144; s++) {
        const int buf = s & 1;
        CP_WAIT0();
        __syncthreads();
        if (s + 1 < 144) issue_stage(s + 1, buf ^ 1);
        const uint32_t ab = sbase + buf * 2 * TILE_B;
        const uint32_t bb = ab + TILE_B;
#pragma unroll
        for (int ks = 0; ks < 2; ks++) {
            uint32_t af[2][4], bf[4][4];
            ldsm4(af[0], ab + aOff[0] + ks * 32);
            ldsm4(af[1], ab + aOff[1] + ks * 32);
#pragma unroll
            for (int nj = 0; nj < 4; nj++) ldsm4(bf[nj], bb + bOff[nj] + ks * 32);
#pragma unroll
            for (int mi = 0; mi < 2; mi++)
#pragma unroll
                for (int ni = 0; ni < 8; ni++)
                    mma16816(acc[mi][ni], af[mi], &bf[ni >> 1][(ni & 1) * 2]);
        }
    }

    const int rb = bm * 128 + wm * 32 + (l >> 2);
    const int cb = bn * 128 + wn * 64 + 2 * (l & 3);
#pragma unroll
    for (int mi = 0; mi < 2; mi++)
#pragma unroll
        for (int ni = 0; ni < 8; ni++) {
            const int row = rb + mi * 16, col = cb + ni * 8;
            *(float2*)&g_q[(size_t)row * NQ + col]       = make_float2(acc[mi][ni][0], acc[mi][ni][1]);
            *(float2*)&g_q[(size_t)(row + 8) * NQ + col] = make_float2(acc[mi][ni][2], acc[mi][ni][3]);
        }
}

// ------------------- fp32 SGEMM for k = x @ wk_w (split-K partials) -------------------
__global__ __launch_bounds__(256) void sgemm_k(
    const float* __restrict__ A, const float* __restrict__ B)
{
    __shared__ float As[8][132];
    __shared__ float Bs[8][132];

    const int tid = threadIdx.x;
    const int tx = tid & 15, ty = tid >> 4;
    const float* Ab = A + (size_t)blockIdx.x * 128 * HID;
    float* Cb = g_kpart + (size_t)blockIdx.z * T_SEQ * HD + (size_t)blockIdx.x * 128 * HD;

    const int arow = tid >> 1, aoff = (tid & 1) * 4;
    const int bkk = tid >> 5, bcol = (tid & 31) * 4;

    float acc[8][8];
#pragma unroll
    for (int i = 0; i < 8; i++)
#pragma unroll
        for (int j = 0; j < 8; j++) acc[i][j] = 0.0f;

    int k0 = blockIdx.z * KCHUNK;
    const int kend = k0 + KCHUNK;
    for (; k0 < kend; k0 += 8) {
        float4 av = *(const float4*)(Ab + (size_t)arow * HID + k0 + aoff);
        float4 bv = *(const float4*)(B + (size_t)(k0 + bkk) * HD + bcol);
        As[aoff + 0][arow] = av.x; As[aoff + 1][arow] = av.y;
        As[aoff + 2][arow] = av.z; As[aoff + 3][arow] = av.w;
        *(float4*)&Bs[bkk][bcol] = bv;
        __syncthreads();
#pragma unroll
        for (int kk = 0; kk < 8; kk++) {
            float4 a0 = *(const float4*)&As[kk][ty * 8];
            float4 a1 = *(const float4*)&As[kk][ty * 8 + 4];
            float4 b0 = *(const float4*)&Bs[kk][tx * 8];
            float4 b1 = *(const float4*)&Bs[kk][tx * 8 + 4];
            float a[8] = {a0.x, a0.y, a0.z, a0.w, a1.x, a1.y, a1.z, a1.w};
            float b[8] = {b0.x, b0.y, b0.z, b0.w, b1.x, b1.y, b1.z, b1.w};
#pragma unroll
            for (int i = 0; i < 8; i++)
#pragma unroll
                for (int j = 0; j < 8; j++)
                    acc[i][j] = fmaf(a[i], b[j], acc[i][j]);
        }
        __syncthreads();
    }
#pragma unroll
    for (int i = 0; i < 8; i++) {
        float* cr = Cb + (size_t)(ty * 8 + i) * HD + tx * 8;
        *(float4*)cr       = make_float4(acc[i][0], acc[i][1], acc[i][2], acc[i][3]);
        *(float4*)(cr + 4) = make_float4(acc[i][4], acc[i][5], acc[i][6], acc[i][7]);
    }
}

// ------------------- split-K reduce + LayerNorm + RoPE + fp16x2 split for k -------------
__global__ __launch_bounds__(128) void k_postproc(
    const float* __restrict__ gamma, const float* __restrict__ beta,
    const float* __restrict__ fcos, const float* __restrict__ fsin)
{
    const int t = blockIdx.x;
    const int d = threadIdx.x;
    float v = 0.0f;
#pragma unroll
    for (int p = 0; p < KSPLIT; p++)
        v += g_kpart[(size_t)p * T_SEQ * HD + (size_t)t * HD + d];

    __shared__ float red[128];
    __shared__ float buf[128];
    red[d] = v; __syncthreads();
#pragma unroll
    for (int s = 64; s > 0; s >>= 1) { if (d < s) red[d] += red[d + s]; __syncthreads(); }
    const float mu = red[0] * (1.0f / 128.0f);
    __syncthreads();
    const float diff = v - mu;
    red[d] = diff * diff; __syncthreads();
#pragma unroll
    for (int s = 64; s > 0; s >>= 1) { if (d < s) red[d] += red[d + s]; __syncthreads(); }
    const float var = red[0] * (1.0f / 128.0f);
    const float inv = __frsqrt_rn(var + 1e-6f);
    const float nrm = diff * inv * gamma[d] + beta[d];
    buf[d] = nrm; __syncthreads();

    float outv;
    if (d < 32) {
        float c = fcos[t * 32 + d], s = fsin[t * 32 + d];
        outv = buf[d] * c - buf[d + 32] * s;
    } else if (d < 64) {
        float c = fcos[t * 32 + d - 32], s = fsin[t * 32 + d - 32];
        outv = buf[d - 32] * s + buf[d] * c;
    } else {
        outv = nrm;
    }
    __half h0 = __float2half_rn(outv);
    float r1 = outv - __half2float(h0);
    const size_t o = (size_t)t * HD + d;
    g_ks0[o] = h0; g_ks1[o] = __float2half_rn(r1);
}

// ------------------- RoPE on q (fp32, in place) -------------------
__global__ void q_rope(const float* __restrict__ fcos, const float* __restrict__ fsin)
{
    int idx = blockIdx.x * blockDim.x + threadIdx.x;
    if (idx >= TQ * NH * 32) return;
    int i = idx & 31;
    int h = (idx >> 5) & 63;
    int tq = idx >> 11;
    int t = TB + tq;
    float c = fcos[t * 32 + i], s = fsin[t * 32 + i];
    float* q = g_q + (size_t)tq * NQ + h * HD;
    float x1 = q[i], x2 = q[i + 32];
    q[i]      = x1 * c - x2 * s;
    q[i + 32] = x1 * s + x2 * c;
}

// ------------------- fp16x2 split of q (post-rope) -------------------
__global__ void q_split()
{
    int i = blockIdx.x * blockDim.x + threadIdx.x;
    if (i >= TQ * NQ) return;
    float v = g_q[i];
    __half h0 = __float2half_rn(v);
    float r1 = v - __half2float(h0);
    g_qs0[i] = h0; g_qs1[i] = __float2half_rn(r1);
}

// ------------------- fp16x2 split of qr active rows -------------------
__global__ void qr_split(const float* __restrict__ qr)
{
    int i = blockIdx.x * blockDim.x + threadIdx.x;
    if (i >= TQ * QLRD) return;
    float v = qr[(size_t)TB * QLRD + i];
    __half h0 = __float2half_rn(v);
    float r1 = v - __half2float(h0);
    g_qrs0[i] = h0; g_qrs1[i] = __float2half_rn(r1);
}

// ------------------- transpose + fp16x2 split of wq_b -> [NQ][QLRD] -------------------
__global__ __launch_bounds__(256) void wq_tsplit(const float* __restrict__ wq_b)
{
    __shared__ float t[32][33];
    const int bx = blockIdx.x;  // n/32
    const int by = blockIdx.y;  // k/32
    const int tx = threadIdx.x & 31, ty = threadIdx.x >> 5;
#pragma unroll
    for (int i = 0; i < 4; i++) {
        int k = by * 32 + ty + i * 8;
        t[ty + i * 8][tx] = wq_b[(size_t)k * NQ + bx * 32 + tx];
    }
    __syncthreads();
#pragma unroll
    for (int i = 0; i < 4; i++) {
        int n = bx * 32 + ty + i * 8;
        float v = t[tx][ty + i * 8];
        __half h0 = __float2half_rn(v);
        float r1 = v - __half2float(h0);
        size_t o = (size_t)n * QLRD + by * 32 + tx;
        g_wqT0[o] = h0; g_wqT1[o] = __float2half_rn(r1);
    }
}

// ------------------- weights for active rows -------------------
__global__ __launch_bounds__(256) void w_gemv(const float* __restrict__ x, const float* __restrict__ wproj)
{
    const int tq = blockIdx.x;
    const int tid = threadIdx.x;
    const int h = tid & 63;
    const int kg = tid >> 6;
    const float* xr = x + (size_t)(TB + tq) * HID + (size_t)kg * (HID / 4);
    const float* wp = wproj + (size_t)kg * (HID / 4) * NH + h;
    float acc = 0.0f;
    for (int k = 0; k < HID / 4; k += 4) {
        float4 xv = *(const float4*)(xr + k);
        acc = fmaf(xv.x, wp[(k + 0) * NH], acc);
        acc = fmaf(xv.y, wp[(k + 1) * NH], acc);
        acc = fmaf(xv.z, wp[(k + 2) * NH], acc);
        acc = fmaf(xv.w, wp[(k + 3) * NH], acc);
    }
    __shared__ float red[4][64];
    red[kg][h] = acc; __syncthreads();
    if (tid < 64) {
        float s = red[0][tid] + red[1][tid] + red[2][tid] + red[3][tid];
        s = (s * 0.125f) * 0.08838834764831843f;
        g_w[tq * NH + tid] = s;
    }
}

// ------------------- fixed fill for rows t < 2048 -------------------
__global__ void fill_fixed(float* __restrict__ out)
{
    size_t i = (size_t)blockIdx.x * blockDim.x + threadIdx.x;
    const size_t total = (size_t)TB * T_SEQ / 4;
    if (i >= total) return;
    size_t s4 = (i % (T_SEQ / 4)) * 4;
    float v = (s4 < TB) ? 0.0f : NEGBIG;
    ((float4*)out)[i] = make_float4(v, v, v, v);
}

// ------------------- exact top-2048 via radix select -------------------
__global__ __launch_bounds__(256) void topk_select(float* __restrict__ out)
{
    __shared__ unsigned keys[T_SEQ];
    __shared__ unsigned char flags[T_SEQ];
    __shared__ int redc[9];
    __shared__ int rlt[8], req[8];
    __shared__ int cnts[256];

    const int tq = blockIdx.x;
    const int t = TB + tq;
    const int n = t + 1;
    const int tid = threadIdx.x;
    const int lane = tid & 31, wid = tid >> 5;
    const float* srow = g_score + (size_t)tq * T_SEQ;

    for (int i = tid; i < n; i += 256) {
        unsigned b = __float_as_uint(srow[i]);
        keys[i] = b ^ ((b & 0x80000000u) ? 0xFFFFFFFFu : 0x80000000u);
    }
    __syncthreads();

    const int m0 = tq + 1;
    int m = m0;
    unsigned prefix = 0;
    for (int bit = 31; bit >= 0; bit--) {
        const unsigned pshift = prefix >> bit;
        int c = 0;
        for (int i = tid; i < n; i += 256)
            c += ((keys[i] >> bit) == pshift);
#pragma unroll
        for (int o = 16; o; o >>= 1) c += __shfl_xor_sync(0xffffffffu, c, o);
        if (lane == 0) redc[wid] = c;
        __syncthreads();
        if (tid == 0) {
            int tot = 0;
            for (int w = 0; w < 8; w++) tot += redc[w];
            redc[8] = tot;
        }
        __syncthreads();
        const int cnt = redc[8];
        if (m > cnt) { m -= cnt; prefix |= (1u << bit); }
        __syncthreads();
    }
    const unsigned theta = prefix;

    int clt = 0, ceq = 0;
    for (int i = tid; i < n; i += 256) {
        unsigned k = keys[i];
        clt += (k < theta);
        ceq += (k == theta);
    }
#pragma unroll
    for (int o = 16; o; o >>= 1) {
        clt += __shfl_xor_sync(0xffffffffu, clt, o);
        ceq += __shfl_xor_sync(0xffffffffu, ceq, o);
    }
    if (lane == 0) { rlt[wid] = clt; req[wid] = ceq; }
    __syncthreads();
    int count_lt = 0, count_eq = 0;
    for (int w = 0; w < 8; w++) { count_lt += rlt[w]; count_eq += req[w]; }
    const int keep_eq = count_eq - (m0 - count_lt);

    const int chunk = (n + 255) / 256;
    const int beg = tid * chunk;
    const int end = (beg + chunk < n) ? (beg + chunk) : n;
    int local = 0;
    for (int i = beg; i < end; i++) local += (keys[i] == theta);
    cnts[tid] = local;
    __syncthreads();
    if (tid == 0) {
        int run = 0;
        for (int i = 0; i < 256; i++) { int c = cnts[i]; cnts[i] = run; run += c; }
    }
    __syncthreads();
    int rank = cnts[tid];
    for (int i = beg; i < end; i++)
        if (keys[i] == theta) { flags[i] = (rank < keep_eq) ? 1 : 0; rank++; }
    __syncthreads();

    float* orow = out + (size_t)t * T_SEQ;
    for (int s = tid; s < T_SEQ; s += 256) {
        float v = NEGBIG;
        if (s < n) {
            unsigned k = keys[s];
            if (k > theta || (k == theta && flags[s])) v = 0.0f;
        }
        orow[s] = v;
    }
}

// ------------------- launch -------------------
extern "C" void kernel_launch(void* const* d_in, const int* in_sizes, int n_in,
                              void* d_out, int out_size)
{
    (void)in_sizes; (void)n_in; (void)out_size;
    const float* x     = (const float*)d_in[0];
    const float* qr    = (const float*)d_in[1];
    const float* fcos  = (const float*)d_in[2];
    const float* fsin  = (const float*)d_in[3];
    const float* wq_b  = (const float*)d_in[5];
    const float* wk_w  = (const float*)d_in[6];
    const float* kgam  = (const float*)d_in[7];
    const float* kbet  = (const float*)d_in[8];
    const float* wproj = (const float*)d_in[9];
    float* out = (float*)d_out;

    sgemm_k<<<dim3(20, 1, KSPLIT), 256>>>(x, wk_w);
    k_postproc<<<T_SEQ, 128>>>(kgam, kbet, fcos, fsin);
    w_gemv<<<TQ, 256>>>(x, wproj);
    qr_split<<<(TQ * QLRD + 255) / 256, 256>>>(qr);
    wq_tsplit<<<dim3(NQ / 32, QLRD / 32), 256>>>(wq_b);
    q_mma<<<dim3(NQ / 128, TQ / 128), 256>>>();
    q_rope<<<(TQ * NH * 32 + 255) / 256, 256>>>(fcos, fsin);
    q_split<<<(TQ * NQ + 255) / 256, 256>>>();
    score_mma<<<dim3(T_SEQ / 128, 256), 256>>>();
    fill_fixed<<<((TB * T_SEQ / 4) + 255) / 256, 256>>>(out);
    topk_select<<<TQ, 256>>>(out);
}

// round 10
// speedup vs baseline: 1.6077x; 1.0317x over previous
#include <cuda_runtime.h>
#include <cuda_fp16.h>
#include <stdint.h>

#define T_SEQ 2560
#define HID   7168
#define QLRD  1536
#define NH    64
#define HD    128
#define NQ    8192
#define TQ    512
#define TB    2048
#define KSPLIT 8
#define KCHUNK (HID / KSPLIT)
#define NEGBIG (-1000000000.0f)

// ------------------- device scratch -------------------
__device__ __align__(16) float g_kpart[KSPLIT * T_SEQ * HD];
__device__ __align__(16) float g_q[TQ * NQ];
__device__ __align__(16) float g_w[TQ * NH];
__device__ __align__(16) float g_score[TQ * T_SEQ];
// fp16 2-way splits
__device__ __align__(16) __half g_qs0[TQ * NQ];
__device__ __align__(16) __half g_qs1[TQ * NQ];
__device__ __align__(16) __half g_ks0[T_SEQ * HD];
__device__ __align__(16) __half g_ks1[T_SEQ * HD];
__device__ __align__(16) __half g_qrs0[TQ * QLRD];
__device__ __align__(16) __half g_qrs1[TQ * QLRD];
__device__ __align__(16) __half g_wqT0[NQ * QLRD];
__device__ __align__(16) __half g_wqT1[NQ * QLRD];

// ------------------- mma.sync / cp.async helpers (baseline PTX) -------------------
__device__ __forceinline__ void ldsm4(uint32_t* r, uint32_t addr) {
    asm volatile("ldmatrix.sync.aligned.m8n8.x4.shared.b16 {%0,%1,%2,%3},[%4];"
        : "=r"(r[0]), "=r"(r[1]), "=r"(r[2]), "=r"(r[3]) : "r"(addr));
}
__device__ __forceinline__ void mma16816(float* d, const uint32_t* a, const uint32_t* b) {
    asm volatile("mma.sync.aligned.m16n8k16.row.col.f32.f16.f16.f32 "
        "{%0,%1,%2,%3},{%4,%5,%6,%7},{%8,%9},{%0,%1,%2,%3};"
        : "+f"(d[0]), "+f"(d[1]), "+f"(d[2]), "+f"(d[3])
        : "r"(a[0]), "r"(a[1]), "r"(a[2]), "r"(a[3]), "r"(b[0]), "r"(b[1]));
}
__device__ __forceinline__ void cpa16(uint32_t dst, const void* src) {
    asm volatile("cp.async.cg.shared.global [%0],[%1],16;" :: "r"(dst), "l"(src));
}
#define CP_COMMIT() asm volatile("cp.async.commit_group;" ::: "memory")
#define CP_WAIT0()  asm volatile("cp.async.wait_group 0;" ::: "memory")

__constant__ int c_aidx[3] = {0, 0, 1};
__constant__ int c_bidx[3] = {0, 1, 0};

#define LDT 40
#define TILE_B (128 * LDT * 2)

// ------------------- score: pipelined HMMA fp16 2-split/3-product + fused epilogue -----
__global__ __launch_bounds__(256, 2) void score_mma()
{
    __shared__ __half sT[2][2][128 * LDT];
    __shared__ float part[8][64];

    const int bs = blockIdx.x, bt = blockIdx.y;
    if (bs * 128 > TB + 2 * bt + 1) return;   // causal skip

    const int tid = threadIdx.x, l = tid & 31, wid = tid >> 5;
    const int wm = wid & 3, wn = wid >> 2;

    const __half* qa[2] = {g_qs0, g_qs1};
    const __half* kb[2] = {g_ks0, g_ks1};

    float acc[2][8][4] = {};

    const uint32_t sbase = (uint32_t)__cvta_generic_to_shared(&sT[0][0][0]);
    const int r0 = (tid + 0) >> 2,   g0 = (tid + 0) & 3;
    const int r1 = (tid + 256) >> 2, g1 = (tid + 256) & 3;

    uint32_t aOff[2], bOff[4];
#pragma unroll
    for (int mi = 0; mi < 2; mi++)
        aOff[mi] = ((wm * 32 + mi * 16 + (l & 15)) * LDT + (l >> 4) * 8) * 2;
#pragma unroll
    for (int nj = 0; nj < 4; nj++)
        bOff[nj] = ((wn * 64 + nj * 16 + ((l >> 4) * 8) + (l & 7)) * LDT + ((l >> 3) & 1) * 8) * 2;

    auto issue_stage = [&](int s, int buf) {
        const int p = s >> 2, kc = s & 3;
        const __half* asrc = qa[c_aidx[p]] + (size_t)bt * 128 * HD + kc * 32;
        const __half* bsrc = kb[c_bidx[p]] + (size_t)bs * 128 * HD + kc * 32;
        const uint32_t ab = sbase + buf * 2 * TILE_B;
        const uint32_t bb = ab + TILE_B;
        cpa16(ab + (r0 * LDT + g0 * 8) * 2, asrc + (size_t)r0 * HD + g0 * 8);
        cpa16(ab + (r1 * LDT + g1 * 8) * 2, asrc + (size_t)r1 * HD + g1 * 8);
        cpa16(bb + (r0 * LDT + g0 * 8) * 2, bsrc + (size_t)r0 * HD + g0 * 8);
        cpa16(bb + (r1 * LDT + g1 * 8) * 2, bsrc + (size_t)r1 * HD + g1 * 8);
        CP_COMMIT();
    };

    issue_stage(0, 0);
#pragma unroll 1
    for (int s = 0; s < 12; s++) {
        const int buf = s & 1;
        CP_WAIT0();
        __syncthreads();
        if (s + 1 < 12) issue_stage(s + 1, buf ^ 1);
        const uint32_t ab = sbase + buf * 2 * TILE_B;
        const uint32_t bb = ab + TILE_B;
#pragma unroll
        for (int ks = 0; ks < 2; ks++) {
            uint32_t af[2][4], bf[4][4];
            ldsm4(af[0], ab + aOff[0] + ks * 32);
            ldsm4(af[1], ab + aOff[1] + ks * 32);
#pragma unroll
            for (int nj = 0; nj < 4; nj++) ldsm4(bf[nj], bb + bOff[nj] + ks * 32);
#pragma unroll
            for (int mi = 0; mi < 2; mi++)
#pragma unroll
                for (int ni = 0; ni < 8; ni++)
                    mma16816(acc[mi][ni], af[mi], &bf[ni >> 1][(ni & 1) * 2]);
        }
    }

    const int rbase = wm * 32 + (l >> 2);
    const float w0 = g_w[bt * 128 + rbase];
    const float w1 = g_w[bt * 128 + rbase + 8];
    const float w2 = g_w[bt * 128 + rbase + 16];
    const float w3 = g_w[bt * 128 + rbase + 24];
#pragma unroll
    for (int ni = 0; ni < 8; ni++) {
        float s0 = fmaxf(acc[0][ni][0], 0.0f) * w0 + fmaxf(acc[0][ni][2], 0.0f) * w1
                 + fmaxf(acc[1][ni][0], 0.0f) * w2 + fmaxf(acc[1][ni][2], 0.0f) * w3;
        float s1 = fmaxf(acc[0][ni][1], 0.0f) * w0 + fmaxf(acc[0][ni][3], 0.0f) * w1
                 + fmaxf(acc[1][ni][1], 0.0f) * w2 + fmaxf(acc[1][ni][3], 0.0f) * w3;
#pragma unroll
        for (int o = 4; o < 32; o <<= 1) {
            s0 += __shfl_xor_sync(0xffffffffu, s0, o);
            s1 += __shfl_xor_sync(0xffffffffu, s1, o);
        }
        if (l < 4) {
            part[wid][ni * 8 + 2 * l] = s0;
            part[wid][ni * 8 + 2 * l + 1] = s1;
        }
    }
    __syncthreads();
    {
        const int col = tid & 127, tt = tid >> 7;
        const int wa = (col >> 6) * 4 + tt * 2;
        float s = part[wa][col & 63] + part[wa + 1][col & 63];
        g_score[(size_t)(bt * 2 + tt) * T_SEQ + bs * 128 + col] = s;
    }
}

// ------------------- q = qr @ wq_b: 128x128 HMMA, 144 stages --------------
__global__ __launch_bounds__(256, 2) void q_mma()
{
    __shared__ __half sT[2][2][128 * LDT];

    const int bn = blockIdx.x, bm = blockIdx.y;
    const int tid = threadIdx.x, l = tid & 31, wid = tid >> 5;
    const int wm = wid & 3, wn = wid >> 2;

    const __half* qa[2] = {g_qrs0, g_qrs1};
    const __half* wb[2] = {g_wqT0, g_wqT1};

    float acc[2][8][4] = {};

    const uint32_t sbase = (uint32_t)__cvta_generic_to_shared(&sT[0][0][0]);
    const int r0 = (tid + 0) >> 2,   g0 = (tid + 0) & 3;
    const int r1 = (tid + 256) >> 2, g1 = (tid + 256) & 3;

    uint32_t aOff[2], bOff[4];
#pragma unroll
    for (int mi = 0; mi < 2; mi++)
        aOff[mi] = ((wm * 32 + mi * 16 + (l & 15)) * LDT + (l >> 4) * 8) * 2;
#pragma unroll
    for (int nj = 0; nj < 4; nj++)
        bOff[nj] = ((wn * 64 + nj * 16 + ((l >> 4) * 8) + (l & 7)) * LDT + ((l >> 3) & 1) * 8) * 2;

    auto issue_stage = [&](int s, int buf) {
        const int p = s / 48, kc = s % 48;
        const __half* asrc = qa[c_aidx[p]] + (size_t)bm * 128 * QLRD + kc * 32;
        const __half* bsrc = wb[c_bidx[p]] + (size_t)bn * 128 * QLRD + kc * 32;
        const uint32_t ab = sbase + buf * 2 * TILE_B;
        const uint32_t bb = ab + TILE_B;
        cpa16(ab + (r0 * LDT + g0 * 8) * 2, asrc + (size_t)r0 * QLRD + g0 * 8);
        cpa16(ab + (r1 * LDT + g1 * 8) * 2, asrc + (size_t)r1 * QLRD + g1 * 8);
        cpa16(bb + (r0 * LDT + g0 * 8) * 2, bsrc + (size_t)r0 * QLRD + g0 * 8);
        cpa16(bb + (r1 * LDT + g1 * 8) * 2, bsrc + (size_t)r1 * QLRD + g1 * 8);
        CP_COMMIT();
    };

    issue_stage(0, 0);
#pragma unroll 1
    for (int s = 0; s < 144; s++) {
        const int buf = s & 1;
        CP_WAIT0();
        __syncthreads();
        if (s + 1 < 144) issue_stage(s + 1, buf ^ 1);
        const uint32_t ab = sbase + buf * 2 * TILE_B;
        const uint32_t bb = ab + TILE_B;
#pragma unroll
        for (int ks = 0; ks < 2; ks++) {
            uint32_t af[2][4], bf[4][4];
            ldsm4(af[0], ab + aOff[0] + ks * 32);
            ldsm4(af[1], ab + aOff[1] + ks * 32);
#pragma unroll
            for (int nj = 0; nj < 4; nj++) ldsm4(bf[nj], bb + bOff[nj] + ks * 32);
#pragma unroll
            for (int mi = 0; mi < 2; mi++)
#pragma unroll
                for (int ni = 0; ni < 8; ni++)
                    mma16816(acc[mi][ni], af[mi], &bf[ni >> 1][(ni & 1) * 2]);
        }
    }

    const int rb = bm * 128 + wm * 32 + (l >> 2);
    const int cb = bn * 128 + wn * 64 + 2 * (l & 3);
#pragma unroll
    for (int mi = 0; mi < 2; mi++)
#pragma unroll
        for (int ni = 0; ni < 8; ni++) {
            const int row = rb + mi * 16, col = cb + ni * 8;
            *(float2*)&g_q[(size_t)row * NQ + col]       = make_float2(acc[mi][ni][0], acc[mi][ni][1]);
            *(float2*)&g_q[(size_t)(row + 8) * NQ + col] = make_float2(acc[mi][ni][2], acc[mi][ni][3]);
        }
}

// ------------------- fp32 SGEMM for k = x @ wk_w (split-K partials) -------------------
__global__ __launch_bounds__(256) void sgemm_k(
    const float* __restrict__ A, const float* __restrict__ B)
{
    __shared__ float As[8][132];
    __shared__ float Bs[8][132];

    const int tid = threadIdx.x;
    const int tx = tid & 15, ty = tid >> 4;
    const float* Ab = A + (size_t)blockIdx.x * 128 * HID;
    float* Cb = g_kpart + (size_t)blockIdx.z * T_SEQ * HD + (size_t)blockIdx.x * 128 * HD;

    const int arow = tid >> 1, aoff = (tid & 1) * 4;
    const int bkk = tid >> 5, bcol = (tid & 31) * 4;

    float acc[8][8];
#pragma unroll
    for (int i = 0; i < 8; i++)
#pragma unroll
        for (int j = 0; j < 8; j++) acc[i][j] = 0.0f;

    int k0 = blockIdx.z * KCHUNK;
    const int kend = k0 + KCHUNK;
    for (; k0 < kend; k0 += 8) {
        float4 av = *(const float4*)(Ab + (size_t)arow * HID + k0 + aoff);
        float4 bv = *(const float4*)(B + (size_t)(k0 + bkk) * HD + bcol);
        As[aoff + 0][arow] = av.x; As[aoff + 1][arow] = av.y;
        As[aoff + 2][arow] = av.z; As[aoff + 3][arow] = av.w;
        *(float4*)&Bs[bkk][bcol] = bv;
        __syncthreads();
#pragma unroll
        for (int kk = 0; kk < 8; kk++) {
            float4 a0 = *(const float4*)&As[kk][ty * 8];
            float4 a1 = *(const float4*)&As[kk][ty * 8 + 4];
            float4 b0 = *(const float4*)&Bs[kk][tx * 8];
            float4 b1 = *(const float4*)&Bs[kk][tx * 8 + 4];
            float a[8] = {a0.x, a0.y, a0.z, a0.w, a1.x, a1.y, a1.z, a1.w};
            float b[8] = {b0.x, b0.y, b0.z, b0.w, b1.x, b1.y, b1.z, b1.w};
#pragma unroll
            for (int i = 0; i < 8; i++)
#pragma unroll
                for (int j = 0; j < 8; j++)
                    acc[i][j] = fmaf(a[i], b[j], acc[i][j]);
        }
        __syncthreads();
    }
#pragma unroll
    for (int i = 0; i < 8; i++) {
        float* cr = Cb + (size_t)(ty * 8 + i) * HD + tx * 8;
        *(float4*)cr       = make_float4(acc[i][0], acc[i][1], acc[i][2], acc[i][3]);
        *(float4*)(cr + 4) = make_float4(acc[i][4], acc[i][5], acc[i][6], acc[i][7]);
    }
}

// ------------------- split-K reduce + LayerNorm + RoPE + fp16x2 split for k -------------
__global__ __launch_bounds__(128) void k_postproc(
    const float* __restrict__ gamma, const float* __restrict__ beta,
    const float* __restrict__ fcos, const float* __restrict__ fsin)
{
    const int t = blockIdx.x;
    const int d = threadIdx.x;
    float v = 0.0f;
#pragma unroll
    for (int p = 0; p < KSPLIT; p++)
        v += g_kpart[(size_t)p * T_SEQ * HD + (size_t)t * HD + d];

    __shared__ float red[128];
    __shared__ float buf[128];
    red[d] = v; __syncthreads();
#pragma unroll
    for (int s = 64; s > 0; s >>= 1) { if (d < s) red[d] += red[d + s]; __syncthreads(); }
    const float mu = red[0] * (1.0f / 128.0f);
    __syncthreads();
    const float diff = v - mu;
    red[d] = diff * diff; __syncthreads();
#pragma unroll
    for (int s = 64; s > 0; s >>= 1) { if (d < s) red[d] += red[d + s]; __syncthreads(); }
    const float var = red[0] * (1.0f / 128.0f);
    const float inv = __frsqrt_rn(var + 1e-6f);
    const float nrm = diff * inv * gamma[d] + beta[d];
    buf[d] = nrm; __syncthreads();

    float outv;
    if (d < 32) {
        float c = fcos[t * 32 + d], s = fsin[t * 32 + d];
        outv = buf[d] * c - buf[d + 32] * s;
    } else if (d < 64) {
        float c = fcos[t * 32 + d - 32], s = fsin[t * 32 + d - 32];
        outv = buf[d - 32] * s + buf[d] * c;
    } else {
        outv = nrm;
    }
    __half h0 = __float2half_rn(outv);
    float r1 = outv - __half2float(h0);
    const size_t o = (size_t)t * HD + d;
    g_ks0[o] = h0; g_ks1[o] = __float2half_rn(r1);
}

// ------------------- fused RoPE + fp16x2 split of q (g_q becomes dead after this) -------
// grid = TQ*NH/2 blocks of 256 threads; each block handles 2 head-rows of 128
__global__ __launch_bounds__(256) void q_rope_split(
    const float* __restrict__ fcos, const float* __restrict__ fsin)
{
    __shared__ float s[256];
    const int tid = threadIdx.x;
    const int row = blockIdx.x * 2 + (tid >> 7);   // global head-row (tq*64 + h)
    const int d = tid & 127;
    const int t = TB + (row >> 6);

    const float v = g_q[(size_t)row * HD + d];
    s[tid] = v;
    __syncthreads();

    float outv;
    if (d < 32) {
        float c = fcos[t * 32 + d], sn = fsin[t * 32 + d];
        outv = s[tid] * c - s[tid + 32] * sn;
    } else if (d < 64) {
        float c = fcos[t * 32 + d - 32], sn = fsin[t * 32 + d - 32];
        outv = s[tid - 32] * sn + s[tid] * c;
    } else {
        outv = v;
    }
    __half h0 = __float2half_rn(outv);
    float r1 = outv - __half2float(h0);
    const size_t o = (size_t)row * HD + d;
    g_qs0[o] = h0;
    g_qs1[o] = __float2half_rn(r1);
}

// ------------------- fp16x2 split of qr active rows (float4 vectorized) ----------------
__global__ void qr_split(const float* __restrict__ qr)
{
    const int i4 = blockIdx.x * blockDim.x + threadIdx.x;   // float4 index
    if (i4 >= TQ * QLRD / 4) return;
    float4 v = ((const float4*)(qr + (size_t)TB * QLRD))[i4];
    __half2 a0 = make_half2(__float2half_rn(v.x), __float2half_rn(v.y));
    __half2 a1 = make_half2(__float2half_rn(v.z), __float2half_rn(v.w));
    __half2 b0 = make_half2(__float2half_rn(v.x - __half2float(a0.x)),
                            __float2half_rn(v.y - __half2float(a0.y)));
    __half2 b1 = make_half2(__float2half_rn(v.z - __half2float(a1.x)),
                            __float2half_rn(v.w - __half2float(a1.y)));
    ((uint2*)g_qrs0)[i4] = make_uint2(*(uint32_t*)&a0, *(uint32_t*)&a1);
    ((uint2*)g_qrs1)[i4] = make_uint2(*(uint32_t*)&b0, *(uint32_t*)&b1);
}

// ------------------- transpose + fp16x2 split of wq_b -> [NQ][QLRD], vectorized --------
// grid (NQ/64, QLRD/64), 256 threads
__global__ __launch_bounds__(256) void wq_tsplit(const float* __restrict__ wq_b)
{
    __shared__ float s[64][65];
    const int bx = blockIdx.x;  // n / 64
    const int by = blockIdx.y;  // k / 64
    const int tid = threadIdx.x;

    // load 64(k) x 64(n) with float4 (16 float4 per row)
#pragma unroll
    for (int i = 0; i < 4; i++) {
        int fid = tid + i * 256;
        int kr = fid >> 4;
        int nc = (fid & 15) * 4;
        float4 v = *(const float4*)(wq_b + (size_t)(by * 64 + kr) * NQ + bx * 64 + nc);
        s[kr][nc] = v.x; s[kr][nc + 1] = v.y; s[kr][nc + 2] = v.z; s[kr][nc + 3] = v.w;
    }
    __syncthreads();

    // write: task = n*8 + kgroup; 8 halves (16B) per limb per task
#pragma unroll
    for (int i = 0; i < 2; i++) {
        int task = tid + i * 256;
        int n = task >> 3, kg = task & 7;
        __align__(16) __half h0[8];
        __align__(16) __half h1[8];
#pragma unroll
        for (int j = 0; j < 8; j++) {
            float v = s[kg * 8 + j][n];
            __half a = __float2half_rn(v);
            h0[j] = a;
            h1[j] = __float2half_rn(v - __half2float(a));
        }
        size_t o = (size_t)(bx * 64 + n) * QLRD + by * 64 + kg * 8;
        *(uint4*)(g_wqT0 + o) = *(uint4*)h0;
        *(uint4*)(g_wqT1 + o) = *(uint4*)h1;
    }
}

// ------------------- weights for active rows -------------------
__global__ __launch_bounds__(256) void w_gemv(const float* __restrict__ x, const float* __restrict__ wproj)
{
    const int tq = blockIdx.x;
    const int tid = threadIdx.x;
    const int h = tid & 63;
    const int kg = tid >> 6;
    const float* xr = x + (size_t)(TB + tq) * HID + (size_t)kg * (HID / 4);
    const float* wp = wproj + (size_t)kg * (HID / 4) * NH + h;
    float acc = 0.0f;
    for (int k = 0; k < HID / 4; k += 4) {
        float4 xv = *(const float4*)(xr + k);
        acc = fmaf(xv.x, wp[(k + 0) * NH], acc);
        acc = fmaf(xv.y, wp[(k + 1) * NH], acc);
        acc = fmaf(xv.z, wp[(k + 2) * NH], acc);
        acc = fmaf(xv.w, wp[(k + 3) * NH], acc);
    }
    __shared__ float red[4][64];
    red[kg][h] = acc; __syncthreads();
    if (tid < 64) {
        float s = red[0][tid] + red[1][tid] + red[2][tid] + red[3][tid];
        s = (s * 0.125f) * 0.08838834764831843f;
        g_w[tq * NH + tid] = s;
    }
}

// ------------------- fixed fill for rows t < 2048 -------------------
__global__ void fill_fixed(float* __restrict__ out)
{
    size_t i = (size_t)blockIdx.x * blockDim.x + threadIdx.x;
    const size_t total = (size_t)TB * T_SEQ / 4;
    if (i >= total) return;
    size_t s4 = (i % (T_SEQ / 4)) * 4;
    float v = (s4 < TB) ? 0.0f : NEGBIG;
    ((float4*)out)[i] = make_float4(v, v, v, v);
}

// ------------------- exact top-2048 via radix-256 select (4 passes) -------------------
__global__ __launch_bounds__(256) void topk_select(float* __restrict__ out)
{
    __shared__ unsigned keys[T_SEQ];
    __shared__ unsigned char flags[T_SEQ];
    __shared__ int whist[8][256];
    __shared__ int scan_s[256];
    __shared__ int bcast[2];
    __shared__ int rlt[8], req[8];
    __shared__ int cnts[256];

    const int tq = blockIdx.x;
    const int t = TB + tq;
    const int n = t + 1;
    const int tid = threadIdx.x;
    const int lane = tid & 31, wid = tid >> 5;
    const float* srow = g_score + (size_t)tq * T_SEQ;

    for (int i = tid; i < n; i += 256) {
        unsigned b = __float_as_uint(srow[i]);
        keys[i] = b ^ ((b & 0x80000000u) ? 0xFFFFFFFFu : 0x80000000u);
    }
    __syncthreads();

    const int m0 = tq + 1;              // rank (1-based) of the key to find, among smallest
    int m = m0;
    unsigned prefix = 0;
#pragma unroll 1
    for (int pass = 0; pass < 4; pass++) {
        const int shift = 24 - pass * 8;
#pragma unroll
        for (int w = 0; w < 8; w++) whist[w][tid] = 0;
        __syncthreads();
        for (int i = tid; i < n; i += 256) {
            unsigned k = keys[i];
            bool ok = (pass == 0) || ((k >> (shift + 8)) == prefix);
            if (ok) atomicAdd(&whist[wid][(k >> shift) & 255], 1);
        }
        __syncthreads();
        int c = 0;
#pragma unroll
        for (int w = 0; w < 8; w++) c += whist[w][tid];
        scan_s[tid] = c;
        __syncthreads();
        // inclusive Hillis-Steele scan over 256 bins
#pragma unroll
        for (int off = 1; off < 256; off <<= 1) {
            int v = (tid >= off) ? scan_s[tid - off] : 0;
            __syncthreads();
            scan_s[tid] += v;
            __syncthreads();
        }
        const int excl = scan_s[tid] - c;
        if (m > excl && m <= excl + c) { bcast[0] = tid; bcast[1] = m - excl; }
        __syncthreads();
        prefix = (prefix << 8) | (unsigned)bcast[0];
        m = bcast[1];
        __syncthreads();
    }
    const unsigned theta = prefix;      // the m0-th smallest key

    int clt = 0, ceq = 0;
    for (int i = tid; i < n; i += 256) {
        unsigned k = keys[i];
        clt += (k < theta);
        ceq += (k == theta);
    }
#pragma unroll
    for (int o = 16; o; o >>= 1) {
        clt += __shfl_xor_sync(0xffffffffu, clt, o);
        ceq += __shfl_xor_sync(0xffffffffu, ceq, o);
    }
    if (lane == 0) { rlt[wid] = clt; req[wid] = ceq; }
    __syncthreads();
    int count_lt = 0, count_eq = 0;
#pragma unroll
    for (int w = 0; w < 8; w++) { count_lt += rlt[w]; count_eq += req[w]; }
    const int keep_eq = count_eq - (m0 - count_lt);   // keep lowest-index ties

    const int chunk = (n + 255) / 256;
    const int beg = tid * chunk;
    const int end = (beg + chunk < n) ? (beg + chunk) : n;
    int local = 0;
    for (int i = beg; i < end; i++) local += (keys[i] == theta);
    cnts[tid] = local;
    __syncthreads();
    if (tid == 0) {
        int run = 0;
        for (int i = 0; i < 256; i++) { int c = cnts[i]; cnts[i] = run; run += c; }
    }
    __syncthreads();
    int rank = cnts[tid];
    for (int i = beg; i < end; i++)
        if (keys[i] == theta) { flags[i] = (rank < keep_eq) ? 1 : 0; rank++; }
    __syncthreads();

    float* orow = out + (size_t)t * T_SEQ;
    for (int s = tid; s < T_SEQ; s += 256) {
        float v = NEGBIG;
        if (s < n) {
            unsigned k = keys[s];
            if (k > theta || (k == theta && flags[s])) v = 0.0f;
        }
        orow[s] = v;
    }
}

// ------------------- launch -------------------
extern "C" void kernel_launch(void* const* d_in, const int* in_sizes, int n_in,
                              void* d_out, int out_size)
{
    (void)in_sizes; (void)n_in; (void)out_size;
    const float* x     = (const float*)d_in[0];
    const float* qr    = (const float*)d_in[1];
    const float* fcos  = (const float*)d_in[2];
    const float* fsin  = (const float*)d_in[3];
    const float* wq_b  = (const float*)d_in[5];
    const float* wk_w  = (const float*)d_in[6];
    const float* kgam  = (const float*)d_in[7];
    const float* kbet  = (const float*)d_in[8];
    const float* wproj = (const float*)d_in[9];
    float* out = (float*)d_out;

    sgemm_k<<<dim3(20, 1, KSPLIT), 256>>>(x, wk_w);
    k_postproc<<<T_SEQ, 128>>>(kgam, kbet, fcos, fsin);
    w_gemv<<<TQ, 256>>>(x, wproj);
    qr_split<<<(TQ * QLRD / 4 + 255) / 256, 256>>>(qr);
    wq_tsplit<<<dim3(NQ / 64, QLRD / 64), 256>>>(wq_b);
    q_mma<<<dim3(NQ / 128, TQ / 128), 256>>>();
    q_rope_split<<<TQ * NH / 2, 256>>>(fcos, fsin);
    score_mma<<<dim3(T_SEQ / 128, 256), 256>>>();
    fill_fixed<<<((TB * T_SEQ / 4) + 255) / 256, 256>>>(out);
    topk_select<<<TQ, 256>>>(out);
}

// round 13
// speedup vs baseline: 1.7641x; 1.0973x over previous
#include <cuda_runtime.h>
#include <cuda_fp16.h>
#include <stdint.h>

#define T_SEQ 2560
#define HID   7168
#define QLRD  1536
#define NH    64
#define HD    128
#define NQ    8192
#define TQ    512
#define TB    2048
#define KSPLIT 8
#define KCHUNK (HID / KSPLIT)   // 896
#define WSPLIT 32
#define WKCH (HID / WSPLIT)     // 224
#define NEGBIG (-1000000000.0f)

// ------------------- device scratch -------------------
__device__ __align__(16) float g_kpart[KSPLIT * T_SEQ * HD];
__device__ __align__(16) float g_wpart[WSPLIT * TQ * NH];
__device__ __align__(16) float g_q[TQ * NQ];
__device__ __align__(16) float g_w[TQ * NH];
__device__ __align__(16) float g_score[TQ * T_SEQ];
// fp16 2-way splits
__device__ __align__(16) __half g_qs0[TQ * NQ];
__device__ __align__(16) __half g_qs1[TQ * NQ];
__device__ __align__(16) __half g_ks0[T_SEQ * HD];
__device__ __align__(16) __half g_ks1[T_SEQ * HD];
__device__ __align__(16) __half g_qrs0[TQ * QLRD];
__device__ __align__(16) __half g_qrs1[TQ * QLRD];
__device__ __align__(16) __half g_wqT0[NQ * QLRD];
__device__ __align__(16) __half g_wqT1[NQ * QLRD];

// ------------------- mma.sync / cp.async helpers (baseline PTX) -------------------
__device__ __forceinline__ void ldsm4(uint32_t* r, uint32_t addr) {
    asm volatile("ldmatrix.sync.aligned.m8n8.x4.shared.b16 {%0,%1,%2,%3},[%4];"
        : "=r"(r[0]), "=r"(r[1]), "=r"(r[2]), "=r"(r[3]) : "r"(addr));
}
__device__ __forceinline__ void mma16816(float* d, const uint32_t* a, const uint32_t* b) {
    asm volatile("mma.sync.aligned.m16n8k16.row.col.f32.f16.f16.f32 "
        "{%0,%1,%2,%3},{%4,%5,%6,%7},{%8,%9},{%0,%1,%2,%3};"
        : "+f"(d[0]), "+f"(d[1]), "+f"(d[2]), "+f"(d[3])
        : "r"(a[0]), "r"(a[1]), "r"(a[2]), "r"(a[3]), "r"(b[0]), "r"(b[1]));
}
__device__ __forceinline__ void cpa16(uint32_t dst, const void* src) {
    asm volatile("cp.async.cg.shared.global [%0],[%1],16;" :: "r"(dst), "l"(src));
}
#define CP_COMMIT() asm volatile("cp.async.commit_group;" ::: "memory")
#define CP_WAIT0()  asm volatile("cp.async.wait_group 0;" ::: "memory")

__constant__ int c_aidx[3] = {0, 0, 1};
__constant__ int c_bidx[3] = {0, 1, 0};

#define LDT 40
#define TILE_B (128 * LDT * 2)

// ------------------- score: pipelined HMMA fp16 2-split/3-product + fused epilogue -----
__global__ __launch_bounds__(256, 2) void score_mma()
{
    __shared__ __half sT[2][2][128 * LDT];
    __shared__ float part[8][64];

    const int bs = blockIdx.x, bt = blockIdx.y;
    if (bs * 128 > TB + 2 * bt + 1) return;   // causal skip

    const int tid = threadIdx.x, l = tid & 31, wid = tid >> 5;
    const int wm = wid & 3, wn = wid >> 2;

    const __half* qa[2] = {g_qs0, g_qs1};
    const __half* kb[2] = {g_ks0, g_ks1};

    float acc[2][8][4] = {};

    const uint32_t sbase = (uint32_t)__cvta_generic_to_shared(&sT[0][0][0]);
    const int r0 = (tid + 0) >> 2,   g0 = (tid + 0) & 3;
    const int r1 = (tid + 256) >> 2, g1 = (tid + 256) & 3;

    uint32_t aOff[2], bOff[4];
#pragma unroll
    for (int mi = 0; mi < 2; mi++)
        aOff[mi] = ((wm * 32 + mi * 16 + (l & 15)) * LDT + (l >> 4) * 8) * 2;
#pragma unroll
    for (int nj = 0; nj < 4; nj++)
        bOff[nj] = ((wn * 64 + nj * 16 + ((l >> 4) * 8) + (l & 7)) * LDT + ((l >> 3) & 1) * 8) * 2;

    auto issue_stage = [&](int s, int buf) {
        const int p = s >> 2, kc = s & 3;
        const __half* asrc = qa[c_aidx[p]] + (size_t)bt * 128 * HD + kc * 32;
        const __half* bsrc = kb[c_bidx[p]] + (size_t)bs * 128 * HD + kc * 32;
        const uint32_t ab = sbase + buf * 2 * TILE_B;
        const uint32_t bb = ab + TILE_B;
        cpa16(ab + (r0 * LDT + g0 * 8) * 2, asrc + (size_t)r0 * HD + g0 * 8);
        cpa16(ab + (r1 * LDT + g1 * 8) * 2, asrc + (size_t)r1 * HD + g1 * 8);
        cpa16(bb + (r0 * LDT + g0 * 8) * 2, bsrc + (size_t)r0 * HD + g0 * 8);
        cpa16(bb + (r1 * LDT + g1 * 8) * 2, bsrc + (size_t)r1 * HD + g1 * 8);
        CP_COMMIT();
    };

    issue_stage(0, 0);
#pragma unroll 1
    for (int s = 0; s < 12; s++) {
        const int buf = s & 1;
        CP_WAIT0();
        __syncthreads();
        if (s + 1 < 12) issue_stage(s + 1, buf ^ 1);
        const uint32_t ab = sbase + buf * 2 * TILE_B;
        const uint32_t bb = ab + TILE_B;
#pragma unroll
        for (int ks = 0; ks < 2; ks++) {
            uint32_t af[2][4], bf[4][4];
            ldsm4(af[0], ab + aOff[0] + ks * 32);
            ldsm4(af[1], ab + aOff[1] + ks * 32);
#pragma unroll
            for (int nj = 0; nj < 4; nj++) ldsm4(bf[nj], bb + bOff[nj] + ks * 32);
#pragma unroll
            for (int mi = 0; mi < 2; mi++)
#pragma unroll
                for (int ni = 0; ni < 8; ni++)
                    mma16816(acc[mi][ni], af[mi], &bf[ni >> 1][(ni & 1) * 2]);
        }
    }

    const int rbase = wm * 32 + (l >> 2);
    const float w0 = g_w[bt * 128 + rbase];
    const float w1 = g_w[bt * 128 + rbase + 8];
    const float w2 = g_w[bt * 128 + rbase + 16];
    const float w3 = g_w[bt * 128 + rbase + 24];
#pragma unroll
    for (int ni = 0; ni < 8; ni++) {
        float s0 = fmaxf(acc[0][ni][0], 0.0f) * w0 + fmaxf(acc[0][ni][2], 0.0f) * w1
                 + fmaxf(acc[1][ni][0], 0.0f) * w2 + fmaxf(acc[1][ni][2], 0.0f) * w3;
        float s1 = fmaxf(acc[0][ni][1], 0.0f) * w0 + fmaxf(acc[0][ni][3], 0.0f) * w1
                 + fmaxf(acc[1][ni][1], 0.0f) * w2 + fmaxf(acc[1][ni][3], 0.0f) * w3;
#pragma unroll
        for (int o = 4; o < 32; o <<= 1) {
            s0 += __shfl_xor_sync(0xffffffffu, s0, o);
            s1 += __shfl_xor_sync(0xffffffffu, s1, o);
        }
        if (l < 4) {
            part[wid][ni * 8 + 2 * l] = s0;
            part[wid][ni * 8 + 2 * l + 1] = s1;
        }
    }
    __syncthreads();
    {
        const int col = tid & 127, tt = tid >> 7;
        const int wa = (col >> 6) * 4 + tt * 2;
        float s = part[wa][col & 63] + part[wa + 1][col & 63];
        g_score[(size_t)(bt * 2 + tt) * T_SEQ + bs * 128 + col] = s;
    }
}

// ------------------- q = qr @ wq_b: 128x128 HMMA, 144 stages --------------
__global__ __launch_bounds__(256, 2) void q_mma()
{
    __shared__ __half sT[2][2][128 * LDT];

    const int bn = blockIdx.x, bm = blockIdx.y;
    const int tid = threadIdx.x, l = tid & 31, wid = tid >> 5;
    const int wm = wid & 3, wn = wid >> 2;

    const __half* qa[2] = {g_qrs0, g_qrs1};
    const __half* wb[2] = {g_wqT0, g_wqT1};

    float acc[2][8][4] = {};

    const uint32_t sbase = (uint32_t)__cvta_generic_to_shared(&sT[0][0][0]);
    const int r0 = (tid + 0) >> 2,   g0 = (tid + 0) & 3;
    const int r1 = (tid + 256) >> 2, g1 = (tid + 256) & 3;

    uint32_t aOff[2], bOff[4];
#pragma unroll
    for (int mi = 0; mi < 2; mi++)
        aOff[mi] = ((wm * 32 + mi * 16 + (l & 15)) * LDT + (l >> 4) * 8) * 2;
#pragma unroll
    for (int nj = 0; nj < 4; nj++)
        bOff[nj] = ((wn * 64 + nj * 16 + ((l >> 4) * 8) + (l & 7)) * LDT + ((l >> 3) & 1) * 8) * 2;

    auto issue_stage = [&](int s, int buf) {
        const int p = s / 48, kc = s % 48;
        const __half* asrc = qa[c_aidx[p]] + (size_t)bm * 128 * QLRD + kc * 32;
        const __half* bsrc = wb[c_bidx[p]] + (size_t)bn * 128 * QLRD + kc * 32;
        const uint32_t ab = sbase + buf * 2 * TILE_B;
        const uint32_t bb = ab + TILE_B;
        cpa16(ab + (r0 * LDT + g0 * 8) * 2, asrc + (size_t)r0 * QLRD + g0 * 8);
        cpa16(ab + (r1 * LDT + g1 * 8) * 2, asrc + (size_t)r1 * QLRD + g1 * 8);
        cpa16(bb + (r0 * LDT + g0 * 8) * 2, bsrc + (size_t)r0 * QLRD + g0 * 8);
        cpa16(bb + (r1 * LDT + g1 * 8) * 2, bsrc + (size_t)r1 * QLRD + g1 * 8);
        CP_COMMIT();
    };

    issue_stage(0, 0);
#pragma unroll 1
    for (int s = 0; s < 144; s++) {
        const int buf = s & 1;
        CP_WAIT0();
        __syncthreads();
        if (s + 1 < 144) issue_stage(s + 1, buf ^ 1);
        const uint32_t ab = sbase + buf * 2 * TILE_B;
        const uint32_t bb = ab + TILE_B;
#pragma unroll
        for (int ks = 0; ks < 2; ks++) {
            uint32_t af[2][4], bf[4][4];
            ldsm4(af[0], ab + aOff[0] + ks * 32);
            ldsm4(af[1], ab + aOff[1] + ks * 32);
#pragma unroll
            for (int nj = 0; nj < 4; nj++) ldsm4(bf[nj], bb + bOff[nj] + ks * 32);
#pragma unroll
            for (int mi = 0; mi < 2; mi++)
#pragma unroll
                for (int ni = 0; ni < 8; ni++)
                    mma16816(acc[mi][ni], af[mi], &bf[ni >> 1][(ni & 1) * 2]);
        }
    }

    const int rb = bm * 128 + wm * 32 + (l >> 2);
    const int cb = bn * 128 + wn * 64 + 2 * (l & 3);
#pragma unroll
    for (int mi = 0; mi < 2; mi++)
#pragma unroll
        for (int ni = 0; ni < 8; ni++) {
            const int row = rb + mi * 16, col = cb + ni * 8;
            *(float2*)&g_q[(size_t)row * NQ + col]       = make_float2(acc[mi][ni][0], acc[mi][ni][1]);
            *(float2*)&g_q[(size_t)(row + 8) * NQ + col] = make_float2(acc[mi][ni][2], acc[mi][ni][3]);
        }
}

// ------------------- fp32 SGEMM for k = x @ wk_w (split-K partials, proven) -------------
__global__ __launch_bounds__(256) void sgemm_k(
    const float* __restrict__ A, const float* __restrict__ B)
{
    __shared__ float As[8][132];
    __shared__ float Bs[8][132];

    const int tid = threadIdx.x;
    const int tx = tid & 15, ty = tid >> 4;
    const float* Ab = A + (size_t)blockIdx.x * 128 * HID;
    float* Cb = g_kpart + (size_t)blockIdx.z * T_SEQ * HD + (size_t)blockIdx.x * 128 * HD;

    const int arow = tid >> 1, aoff = (tid & 1) * 4;
    const int bkk = tid >> 5, bcol = (tid & 31) * 4;

    float acc[8][8];
#pragma unroll
    for (int i = 0; i < 8; i++)
#pragma unroll
        for (int j = 0; j < 8; j++) acc[i][j] = 0.0f;

    int k0 = blockIdx.z * KCHUNK;
    const int kend = k0 + KCHUNK;
    for (; k0 < kend; k0 += 8) {
        float4 av = *(const float4*)(Ab + (size_t)arow * HID + k0 + aoff);
        float4 bv = *(const float4*)(B + (size_t)(k0 + bkk) * HD + bcol);
        As[aoff + 0][arow] = av.x; As[aoff + 1][arow] = av.y;
        As[aoff + 2][arow] = av.z; As[aoff + 3][arow] = av.w;
        *(float4*)&Bs[bkk][bcol] = bv;
        __syncthreads();
#pragma unroll
        for (int kk = 0; kk < 8; kk++) {
            float4 a0 = *(const float4*)&As[kk][ty * 8];
            float4 a1 = *(const float4*)&As[kk][ty * 8 + 4];
            float4 b0 = *(const float4*)&Bs[kk][tx * 8];
            float4 b1 = *(const float4*)&Bs[kk][tx * 8 + 4];
            float a[8] = {a0.x, a0.y, a0.z, a0.w, a1.x, a1.y, a1.z, a1.w};
            float b[8] = {b0.x, b0.y, b0.z, b0.w, b1.x, b1.y, b1.z, b1.w};
#pragma unroll
            for (int i = 0; i < 8; i++)
#pragma unroll
                for (int j = 0; j < 8; j++)
                    acc[i][j] = fmaf(a[i], b[j], acc[i][j]);
        }
        __syncthreads();
    }
#pragma unroll
    for (int i = 0; i < 8; i++) {
        float* cr = Cb + (size_t)(ty * 8 + i) * HD + tx * 8;
        *(float4*)cr       = make_float4(acc[i][0], acc[i][1], acc[i][2], acc[i][3]);
        *(float4*)(cr + 4) = make_float4(acc[i][4], acc[i][5], acc[i][6], acc[i][7]);
    }
}

// ------------------- split-K reduce + LayerNorm + RoPE + fp16x2 split for k -------------
__global__ __launch_bounds__(128) void k_postproc(
    const float* __restrict__ gamma, const float* __restrict__ beta,
    const float* __restrict__ fcos, const float* __restrict__ fsin)
{
    const int t = blockIdx.x;
    const int d = threadIdx.x;
    float v = 0.0f;
#pragma unroll
    for (int p = 0; p < KSPLIT; p++)
        v += g_kpart[(size_t)p * T_SEQ * HD + (size_t)t * HD + d];

    __shared__ float red[128];
    __shared__ float buf[128];
    red[d] = v; __syncthreads();
#pragma unroll
    for (int s = 64; s > 0; s >>= 1) { if (d < s) red[d] += red[d + s]; __syncthreads(); }
    const float mu = red[0] * (1.0f / 128.0f);
    __syncthreads();
    const float diff = v - mu;
    red[d] = diff * diff; __syncthreads();
#pragma unroll
    for (int s = 64; s > 0; s >>= 1) { if (d < s) red[d] += red[d + s]; __syncthreads(); }
    const float var = red[0] * (1.0f / 128.0f);
    const float inv = __frsqrt_rn(var + 1e-6f);
    const float nrm = diff * inv * gamma[d] + beta[d];
    buf[d] = nrm; __syncthreads();

    float outv;
    if (d < 32) {
        float c = fcos[t * 32 + d], s = fsin[t * 32 + d];
        outv = buf[d] * c - buf[d + 32] * s;
    } else if (d < 64) {
        float c = fcos[t * 32 + d - 32], s = fsin[t * 32 + d - 32];
        outv = buf[d - 32] * s + buf[d] * c;
    } else {
        outv = nrm;
    }
    __half h0 = __float2half_rn(outv);
    float r1 = outv - __half2float(h0);
    const size_t o = (size_t)t * HD + d;
    g_ks0[o] = h0; g_ks1[o] = __float2half_rn(r1);
}

// ------------------- fused RoPE + fp16x2 split of q -------------------
__global__ __launch_bounds__(256) void q_rope_split(
    const float* __restrict__ fcos, const float* __restrict__ fsin)
{
    __shared__ float s[256];
    const int tid = threadIdx.x;
    const int row = blockIdx.x * 2 + (tid >> 7);
    const int d = tid & 127;
    const int t = TB + (row >> 6);

    const float v = g_q[(size_t)row * HD + d];
    s[tid] = v;
    __syncthreads();

    float outv;
    if (d < 32) {
        float c = fcos[t * 32 + d], sn = fsin[t * 32 + d];
        outv = s[tid] * c - s[tid + 32] * sn;
    } else if (d < 64) {
        float c = fcos[t * 32 + d - 32], sn = fsin[t * 32 + d - 32];
        outv = s[tid - 32] * sn + s[tid] * c;
    } else {
        outv = v;
    }
    __half h0 = __float2half_rn(outv);
    float r1 = outv - __half2float(h0);
    const size_t o = (size_t)row * HD + d;
    g_qs0[o] = h0;
    g_qs1[o] = __float2half_rn(r1);
}

// ------------------- fp16x2 split of qr active rows (float4 vectorized) ----------------
__global__ void qr_split(const float* __restrict__ qr)
{
    const int i4 = blockIdx.x * blockDim.x + threadIdx.x;
    if (i4 >= TQ * QLRD / 4) return;
    float4 v = ((const float4*)(qr + (size_t)TB * QLRD))[i4];
    __half2 a0 = make_half2(__float2half_rn(v.x), __float2half_rn(v.y));
    __half2 a1 = make_half2(__float2half_rn(v.z), __float2half_rn(v.w));
    __half2 b0 = make_half2(__float2half_rn(v.x - __half2float(a0.x)),
                            __float2half_rn(v.y - __half2float(a0.y)));
    __half2 b1 = make_half2(__float2half_rn(v.z - __half2float(a1.x)),
                            __float2half_rn(v.w - __half2float(a1.y)));
    ((uint2*)g_qrs0)[i4] = make_uint2(*(uint32_t*)&a0, *(uint32_t*)&a1);
    ((uint2*)g_qrs1)[i4] = make_uint2(*(uint32_t*)&b0, *(uint32_t*)&b1);
}

// ------------------- transpose + fp16x2 split of wq_b -> [NQ][QLRD] (proven R9) ---------
__global__ __launch_bounds__(256) void wq_tsplit(const float* __restrict__ wq_b)
{
    __shared__ float t[32][33];
    const int bx = blockIdx.x;  // n/32
    const int by = blockIdx.y;  // k/32
    const int tx = threadIdx.x & 31, ty = threadIdx.x >> 5;
#pragma unroll
    for (int i = 0; i < 4; i++) {
        int k = by * 32 + ty + i * 8;
        t[ty + i * 8][tx] = wq_b[(size_t)k * NQ + bx * 32 + tx];
    }
    __syncthreads();
#pragma unroll
    for (int i = 0; i < 4; i++) {
        int n = bx * 32 + ty + i * 8;
        float v = t[tx][ty + i * 8];
        __half h0 = __float2half_rn(v);
        float r1 = v - __half2float(h0);
        size_t o = (size_t)n * QLRD + by * 32 + tx;
        g_wqT0[o] = h0; g_wqT1[o] = __float2half_rn(r1);
    }
}

// ------------------- weights: split-K tiled SGEMM (replaces w_gemv) --------------------
// grid (4 m-tiles of 128 rows, 32 k-splits), 256 threads; partials -> g_wpart
__global__ __launch_bounds__(256) void w_gemm(const float* __restrict__ x,
                                              const float* __restrict__ wproj)
{
    __shared__ float As[8][132];
    __shared__ float Bs[8][68];

    const int bm = blockIdx.x;   // 0..3
    const int sp = blockIdx.y;   // 0..31
    const int tid = threadIdx.x;
    const int tx = tid & 15, ty = tid >> 4;
    const float* Ab = x + (size_t)(TB + bm * 128) * HID;

    const int arow = tid >> 1, aoff = (tid & 1) * 4;
    const int bkk = tid >> 4, bcol = (tid & 15) * 4;   // used when tid < 128

    float acc[8][4];
#pragma unroll
    for (int i = 0; i < 8; i++)
#pragma unroll
        for (int j = 0; j < 4; j++) acc[i][j] = 0.0f;

    int k0 = sp * WKCH;
    const int kend = k0 + WKCH;
    for (; k0 < kend; k0 += 8) {
        float4 av = *(const float4*)(Ab + (size_t)arow * HID + k0 + aoff);
        float4 bv = make_float4(0.f, 0.f, 0.f, 0.f);
        if (tid < 128) bv = *(const float4*)(wproj + (size_t)(k0 + bkk) * NH + bcol);
        As[aoff + 0][arow] = av.x; As[aoff + 1][arow] = av.y;
        As[aoff + 2][arow] = av.z; As[aoff + 3][arow] = av.w;
        if (tid < 128) *(float4*)&Bs[bkk][bcol] = bv;
        __syncthreads();
#pragma unroll
        for (int kk = 0; kk < 8; kk++) {
            float a[8], b[4];
            *(float4*)&a[0] = *(const float4*)&As[kk][ty * 8];
            *(float4*)&a[4] = *(const float4*)&As[kk][ty * 8 + 4];
            *(float4*)&b[0] = *(const float4*)&Bs[kk][tx * 4];
#pragma unroll
            for (int i = 0; i < 8; i++)
#pragma unroll
                for (int j = 0; j < 4; j++)
                    acc[i][j] = fmaf(a[i], b[j], acc[i][j]);
        }
        __syncthreads();
    }

    float* Cb = g_wpart + (size_t)sp * TQ * NH + (size_t)bm * 128 * NH;
#pragma unroll
    for (int i = 0; i < 8; i++)
        *(float4*)&Cb[(size_t)(ty * 8 + i) * NH + tx * 4] =
            make_float4(acc[i][0], acc[i][1], acc[i][2], acc[i][3]);
}

// deterministic fixed-order reduce + scale -> g_w
__global__ void w_reduce()
{
    const int i = blockIdx.x * blockDim.x + threadIdx.x;
    if (i >= TQ * NH) return;
    float s = 0.0f;
#pragma unroll
    for (int p = 0; p < WSPLIT; p++)
        s += g_wpart[(size_t)p * TQ * NH + i];
    g_w[i] = (s * 0.125f) * 0.08838834764831843f;
}

// ------------------- fixed fill for rows t < 2048 -------------------
__global__ void fill_fixed(float* __restrict__ out)
{
    size_t i = (size_t)blockIdx.x * blockDim.x + threadIdx.x;
    const size_t total = (size_t)TB * T_SEQ / 4;
    if (i >= total) return;
    size_t s4 = (i % (T_SEQ / 4)) * 4;
    float v = (s4 < TB) ? 0.0f : NEGBIG;
    ((float4*)out)[i] = make_float4(v, v, v, v);
}

// ------------------- exact top-2048 via radix-256 select (4 passes) -------------------
__global__ __launch_bounds__(256) void topk_select(float* __restrict__ out)
{
    __shared__ unsigned keys[T_SEQ];
    __shared__ unsigned char flags[T_SEQ];
    __shared__ int whist[8][256];
    __shared__ int scan_s[256];
    __shared__ int bcast[2];
    __shared__ int rlt[8], req[8];
    __shared__ int cnts[256];

    const int tq = blockIdx.x;
    const int t = TB + tq;
    const int n = t + 1;
    const int tid = threadIdx.x;
    const int lane = tid & 31, wid = tid >> 5;
    const float* srow = g_score + (size_t)tq * T_SEQ;

    for (int i = tid; i < n; i += 256) {
        unsigned b = __float_as_uint(srow[i]);
        keys[i] = b ^ ((b & 0x80000000u) ? 0xFFFFFFFFu : 0x80000000u);
    }
    __syncthreads();

    const int m0 = tq + 1;
    int m = m0;
    unsigned prefix = 0;
#pragma unroll 1
    for (int pass = 0; pass < 4; pass++) {
        const int shift = 24 - pass * 8;
#pragma unroll
        for (int w = 0; w < 8; w++) whist[w][tid] = 0;
        __syncthreads();
        for (int i = tid; i < n; i += 256) {
            unsigned k = keys[i];
            bool ok = (pass == 0) || ((k >> (shift + 8)) == prefix);
            if (ok) atomicAdd(&whist[wid][(k >> shift) & 255], 1);
        }
        __syncthreads();
        int c = 0;
#pragma unroll
        for (int w = 0; w < 8; w++) c += whist[w][tid];
        scan_s[tid] = c;
        __syncthreads();
#pragma unroll
        for (int off = 1; off < 256; off <<= 1) {
            int v = (tid >= off) ? scan_s[tid - off] : 0;
            __syncthreads();
            scan_s[tid] += v;
            __syncthreads();
        }
        const int excl = scan_s[tid] - c;
        if (m > excl && m <= excl + c) { bcast[0] = tid; bcast[1] = m - excl; }
        __syncthreads();
        prefix = (prefix << 8) | (unsigned)bcast[0];
        m = bcast[1];
        __syncthreads();
    }
    const unsigned theta = prefix;

    int clt = 0, ceq = 0;
    for (int i = tid; i < n; i += 256) {
        unsigned k = keys[i];
        clt += (k < theta);
        ceq += (k == theta);
    }
#pragma unroll
    for (int o = 16; o; o >>= 1) {
        clt += __shfl_xor_sync(0xffffffffu, clt, o);
        ceq += __shfl_xor_sync(0xffffffffu, ceq, o);
    }
    if (lane == 0) { rlt[wid] = clt; req[wid] = ceq; }
    __syncthreads();
    int count_lt = 0, count_eq = 0;
#pragma unroll
    for (int w = 0; w < 8; w++) { count_lt += rlt[w]; count_eq += req[w]; }
    const int keep_eq = count_eq - (m0 - count_lt);

    const int chunk = (n + 255) / 256;
    const int beg = tid * chunk;
    const int end = (beg + chunk < n) ? (beg + chunk) : n;
    int local = 0;
    for (int i = beg; i < end; i++) local += (keys[i] == theta);
    cnts[tid] = local;
    __syncthreads();
    if (tid == 0) {
        int run = 0;
        for (int i = 0; i < 256; i++) { int c = cnts[i]; cnts[i] = run; run += c; }
    }
    __syncthreads();
    int rank = cnts[tid];
    for (int i = beg; i < end; i++)
        if (keys[i] == theta) { flags[i] = (rank < keep_eq) ? 1 : 0; rank++; }
    __syncthreads();

    float* orow = out + (size_t)t * T_SEQ;
    for (int s = tid; s < T_SEQ; s += 256) {
        float v = NEGBIG;
        if (s < n) {
            unsigned k = keys[s];
            if (k > theta || (k == theta && flags[s])) v = 0.0f;
        }
        orow[s] = v;
    }
}

// ------------------- launch -------------------
extern "C" void kernel_launch(void* const* d_in, const int* in_sizes, int n_in,
                              void* d_out, int out_size)
{
    (void)in_sizes; (void)n_in; (void)out_size;
    const float* x     = (const float*)d_in[0];
    const float* qr    = (const float*)d_in[1];
    const float* fcos  = (const float*)d_in[2];
    const float* fsin  = (const float*)d_in[3];
    const float* wq_b  = (const float*)d_in[5];
    const float* wk_w  = (const float*)d_in[6];
    const float* kgam  = (const float*)d_in[7];
    const float* kbet  = (const float*)d_in[8];
    const float* wproj = (const float*)d_in[9];
    float* out = (float*)d_out;

    sgemm_k<<<dim3(20, 1, KSPLIT), 256>>>(x, wk_w);
    k_postproc<<<T_SEQ, 128>>>(kgam, kbet, fcos, fsin);
    w_gemm<<<dim3(4, WSPLIT), 256>>>(x, wproj);
    w_reduce<<<(TQ * NH + 255) / 256, 256>>>();
    qr_split<<<(TQ * QLRD / 4 + 255) / 256, 256>>>(qr);
    wq_tsplit<<<dim3(NQ / 32, QLRD / 32), 256>>>(wq_b);
    q_mma<<<dim3(NQ / 128, TQ / 128), 256>>>();
    q_rope_split<<<TQ * NH / 2, 256>>>(fcos, fsin);
    score_mma<<<dim3(T_SEQ / 128, 256), 256>>>();
    fill_fixed<<<((TB * T_SEQ / 4) + 255) / 256, 256>>>(out);
    topk_select<<<TQ, 256>>>(out);
}

// round 14
// speedup vs baseline: 2.2197x; 1.2582x over previous
#include <cuda_runtime.h>
#include <cuda_fp16.h>
#include <stdint.h>

#define T_SEQ 2560
#define HID   7168
#define QLRD  1536
#define NH    64
#define HD    128
#define NQ    8192
#define TQ    512
#define TB    2048
#define KSPLIT 14
#define KCH   (HID / KSPLIT)    // 512
#define WSPLIT 32
#define WKCH (HID / WSPLIT)     // 224
#define NEGBIG (-1000000000.0f)

// ------------------- device scratch -------------------
__device__ __align__(16) float g_kpart[KSPLIT * T_SEQ * HD];
__device__ __align__(16) float g_wpart[WSPLIT * TQ * NH];
__device__ __align__(16) float g_w[TQ * NH];
__device__ __align__(16) float g_score[TQ * T_SEQ];
// fp16 2-way splits
__device__ __align__(16) __half g_qs0[TQ * NQ];
__device__ __align__(16) __half g_qs1[TQ * NQ];
__device__ __align__(16) __half g_ks0[T_SEQ * HD];
__device__ __align__(16) __half g_ks1[T_SEQ * HD];
__device__ __align__(16) __half g_qrs0[TQ * QLRD];
__device__ __align__(16) __half g_qrs1[TQ * QLRD];
__device__ __align__(16) __half g_wqT0[NQ * QLRD];
__device__ __align__(16) __half g_wqT1[NQ * QLRD];
__device__ __align__(16) __half g_wkT0[HD * HID];
__device__ __align__(16) __half g_wkT1[HD * HID];
__device__ __align__(16) __half g_xs0[T_SEQ * HID];
__device__ __align__(16) __half g_xs1[T_SEQ * HID];

// ------------------- mma.sync / cp.async helpers (baseline PTX) -------------------
__device__ __forceinline__ void ldsm4(uint32_t* r, uint32_t addr) {
    asm volatile("ldmatrix.sync.aligned.m8n8.x4.shared.b16 {%0,%1,%2,%3},[%4];"
        : "=r"(r[0]), "=r"(r[1]), "=r"(r[2]), "=r"(r[3]) : "r"(addr));
}
__device__ __forceinline__ void mma16816(float* d, const uint32_t* a, const uint32_t* b) {
    asm volatile("mma.sync.aligned.m16n8k16.row.col.f32.f16.f16.f32 "
        "{%0,%1,%2,%3},{%4,%5,%6,%7},{%8,%9},{%0,%1,%2,%3};"
        : "+f"(d[0]), "+f"(d[1]), "+f"(d[2]), "+f"(d[3])
        : "r"(a[0]), "r"(a[1]), "r"(a[2]), "r"(a[3]), "r"(b[0]), "r"(b[1]));
}
__device__ __forceinline__ void cpa16(uint32_t dst, const void* src) {
    asm volatile("cp.async.cg.shared.global [%0],[%1],16;" :: "r"(dst), "l"(src));
}
#define CP_COMMIT() asm volatile("cp.async.commit_group;" ::: "memory")
#define CP_WAIT0()  asm volatile("cp.async.wait_group 0;" ::: "memory")

__constant__ int c_aidx[3] = {0, 0, 1};
__constant__ int c_bidx[3] = {0, 1, 0};

#define LDT 40
#define TILE_B (128 * LDT * 2)

// ------------------- score: pipelined HMMA fp16 2-split/3-product + fused epilogue -----
__global__ __launch_bounds__(256, 2) void score_mma()
{
    __shared__ __half sT[2][2][128 * LDT];
    __shared__ float part[8][64];

    const int bs = blockIdx.x, bt = blockIdx.y;
    if (bs * 128 > TB + 2 * bt + 1) return;   // causal skip

    const int tid = threadIdx.x, l = tid & 31, wid = tid >> 5;
    const int wm = wid & 3, wn = wid >> 2;

    const __half* qa[2] = {g_qs0, g_qs1};
    const __half* kb[2] = {g_ks0, g_ks1};

    float acc[2][8][4] = {};

    const uint32_t sbase = (uint32_t)__cvta_generic_to_shared(&sT[0][0][0]);
    const int r0 = (tid + 0) >> 2,   g0 = (tid + 0) & 3;
    const int r1 = (tid + 256) >> 2, g1 = (tid + 256) & 3;

    uint32_t aOff[2], bOff[4];
#pragma unroll
    for (int mi = 0; mi < 2; mi++)
        aOff[mi] = ((wm * 32 + mi * 16 + (l & 15)) * LDT + (l >> 4) * 8) * 2;
#pragma unroll
    for (int nj = 0; nj < 4; nj++)
        bOff[nj] = ((wn * 64 + nj * 16 + ((l >> 4) * 8) + (l & 7)) * LDT + ((l >> 3) & 1) * 8) * 2;

    auto issue_stage = [&](int s, int buf) {
        const int p = s >> 2, kc = s & 3;
        const __half* asrc = qa[c_aidx[p]] + (size_t)bt * 128 * HD + kc * 32;
        const __half* bsrc = kb[c_bidx[p]] + (size_t)bs * 128 * HD + kc * 32;
        const uint32_t ab = sbase + buf * 2 * TILE_B;
        const uint32_t bb = ab + TILE_B;
        cpa16(ab + (r0 * LDT + g0 * 8) * 2, asrc + (size_t)r0 * HD + g0 * 8);
        cpa16(ab + (r1 * LDT + g1 * 8) * 2, asrc + (size_t)r1 * HD + g1 * 8);
        cpa16(bb + (r0 * LDT + g0 * 8) * 2, bsrc + (size_t)r0 * HD + g0 * 8);
        cpa16(bb + (r1 * LDT + g1 * 8) * 2, bsrc + (size_t)r1 * HD + g1 * 8);
        CP_COMMIT();
    };

    issue_stage(0, 0);
#pragma unroll 1
    for (int s = 0; s < 12; s++) {
        const int buf = s & 1;
        CP_WAIT0();
        __syncthreads();
        if (s + 1 < 12) issue_stage(s + 1, buf ^ 1);
        const uint32_t ab = sbase + buf * 2 * TILE_B;
        const uint32_t bb = ab + TILE_B;
#pragma unroll
        for (int ks = 0; ks < 2; ks++) {
            uint32_t af[2][4], bf[4][4];
            ldsm4(af[0], ab + aOff[0] + ks * 32);
            ldsm4(af[1], ab + aOff[1] + ks * 32);
#pragma unroll
            for (int nj = 0; nj < 4; nj++) ldsm4(bf[nj], bb + bOff[nj] + ks * 32);
#pragma unroll
            for (int mi = 0; mi < 2; mi++)
#pragma unroll
                for (int ni = 0; ni < 8; ni++)
                    mma16816(acc[mi][ni], af[mi], &bf[ni >> 1][(ni & 1) * 2]);
        }
    }

    const int rbase = wm * 32 + (l >> 2);
    const float w0 = g_w[bt * 128 + rbase];
    const float w1 = g_w[bt * 128 + rbase + 8];
    const float w2 = g_w[bt * 128 + rbase + 16];
    const float w3 = g_w[bt * 128 + rbase + 24];
#pragma unroll
    for (int ni = 0; ni < 8; ni++) {
        float s0 = fmaxf(acc[0][ni][0], 0.0f) * w0 + fmaxf(acc[0][ni][2], 0.0f) * w1
                 + fmaxf(acc[1][ni][0], 0.0f) * w2 + fmaxf(acc[1][ni][2], 0.0f) * w3;
        float s1 = fmaxf(acc[0][ni][1], 0.0f) * w0 + fmaxf(acc[0][ni][3], 0.0f) * w1
                 + fmaxf(acc[1][ni][1], 0.0f) * w2 + fmaxf(acc[1][ni][3], 0.0f) * w3;
#pragma unroll
        for (int o = 4; o < 32; o <<= 1) {
            s0 += __shfl_xor_sync(0xffffffffu, s0, o);
            s1 += __shfl_xor_sync(0xffffffffu, s1, o);
        }
        if (l < 4) {
            part[wid][ni * 8 + 2 * l] = s0;
            part[wid][ni * 8 + 2 * l + 1] = s1;
        }
    }
    __syncthreads();
    {
        const int col = tid & 127, tt = tid >> 7;
        const int wa = (col >> 6) * 4 + tt * 2;
        float s = part[wa][col & 63] + part[wa + 1][col & 63];
        g_score[(size_t)(bt * 2 + tt) * T_SEQ + bs * 128 + col] = s;
    }
}

// ------------------- q = qr @ wq_b: 128x128 HMMA, 144 stages, fused rope+split epilogue --
// grid (64 n-tiles = one head each, 4 m-tiles of 128 tq rows)
__global__ __launch_bounds__(256, 2) void q_mma(
    const float* __restrict__ fcos, const float* __restrict__ fsin)
{
    __shared__ __half sT[2][2][128 * LDT];

    const int bn = blockIdx.x, bm = blockIdx.y;
    const int tid = threadIdx.x, l = tid & 31, wid = tid >> 5;
    const int wm = wid & 3, wn = wid >> 2;

    const __half* qa[2] = {g_qrs0, g_qrs1};
    const __half* wb[2] = {g_wqT0, g_wqT1};

    float acc[2][8][4] = {};

    const uint32_t sbase = (uint32_t)__cvta_generic_to_shared(&sT[0][0][0]);
    const int r0 = (tid + 0) >> 2,   g0 = (tid + 0) & 3;
    const int r1 = (tid + 256) >> 2, g1 = (tid + 256) & 3;

    uint32_t aOff[2], bOff[4];
#pragma unroll
    for (int mi = 0; mi < 2; mi++)
        aOff[mi] = ((wm * 32 + mi * 16 + (l & 15)) * LDT + (l >> 4) * 8) * 2;
#pragma unroll
    for (int nj = 0; nj < 4; nj++)
        bOff[nj] = ((wn * 64 + nj * 16 + ((l >> 4) * 8) + (l & 7)) * LDT + ((l >> 3) & 1) * 8) * 2;

    auto issue_stage = [&](int s, int buf) {
        const int p = s / 48, kc = s % 48;
        const __half* asrc = qa[c_aidx[p]] + (size_t)bm * 128 * QLRD + kc * 32;
        const __half* bsrc = wb[c_bidx[p]] + (size_t)bn * 128 * QLRD + kc * 32;
        const uint32_t ab = sbase + buf * 2 * TILE_B;
        const uint32_t bb = ab + TILE_B;
        cpa16(ab + (r0 * LDT + g0 * 8) * 2, asrc + (size_t)r0 * QLRD + g0 * 8);
        cpa16(ab + (r1 * LDT + g1 * 8) * 2, asrc + (size_t)r1 * QLRD + g1 * 8);
        cpa16(bb + (r0 * LDT + g0 * 8) * 2, bsrc + (size_t)r0 * QLRD + g0 * 8);
        cpa16(bb + (r1 * LDT + g1 * 8) * 2, bsrc + (size_t)r1 * QLRD + g1 * 8);
        CP_COMMIT();
    };

    issue_stage(0, 0);
#pragma unroll 1
    for (int s = 0; s < 144; s++) {
        const int buf = s & 1;
        CP_WAIT0();
        __syncthreads();
        if (s + 1 < 144) issue_stage(s + 1, buf ^ 1);
        const uint32_t ab = sbase + buf * 2 * TILE_B;
        const uint32_t bb = ab + TILE_B;
#pragma unroll
        for (int ks = 0; ks < 2; ks++) {
            uint32_t af[2][4], bf[4][4];
            ldsm4(af[0], ab + aOff[0] + ks * 32);
            ldsm4(af[1], ab + aOff[1] + ks * 32);
#pragma unroll
            for (int nj = 0; nj < 4; nj++) ldsm4(bf[nj], bb + bOff[nj] + ks * 32);
#pragma unroll
            for (int mi = 0; mi < 2; mi++)
#pragma unroll
                for (int ni = 0; ni < 8; ni++)
                    mma16816(acc[mi][ni], af[mi], &bf[ni >> 1][(ni & 1) * 2]);
        }
    }

    // ---- fused epilogue: rope on dims [0,64) (wn==0), fp16x2 split, store g_qs ----
    const int tq0 = bm * 128 + wm * 32 + (l >> 2);
    const int h = bn;
    if (wn == 0) {
#pragma unroll
        for (int mi = 0; mi < 2; mi++)
#pragma unroll
            for (int ni = 0; ni < 4; ni++) {
                const int d = 2 * (l & 3) + ni * 8;        // even, < 32
#pragma unroll
                for (int rr = 0; rr < 2; rr++) {
                    const int row = tq0 + mi * 16 + rr * 8;
                    const int t = TB + row;
                    const float c0 = fcos[t * 32 + d],     s0 = fsin[t * 32 + d];
                    const float c1 = fcos[t * 32 + d + 1], s1 = fsin[t * 32 + d + 1];
                    const float x1a = acc[mi][ni][rr * 2],     x1b = acc[mi][ni][rr * 2 + 1];
                    const float x2a = acc[mi][ni + 4][rr * 2], x2b = acc[mi][ni + 4][rr * 2 + 1];
                    const float oa = x1a * c0 - x2a * s0, ob = x1b * c1 - x2b * s1;
                    const float pa = x1a * s0 + x2a * c0, pb = x1b * s1 + x2b * c1;
                    const size_t base = ((size_t)row * NH + h) * HD;
                    __half ha = __float2half_rn(oa), hb = __float2half_rn(ob);
                    __half hc = __float2half_rn(pa), hd2 = __float2half_rn(pb);
                    *(__half2*)&g_qs0[base + d]      = __halves2half2(ha, hb);
                    *(__half2*)&g_qs0[base + d + 32] = __halves2half2(hc, hd2);
                    *(__half2*)&g_qs1[base + d] = __halves2half2(
                        __float2half_rn(oa - __half2float(ha)),
                        __float2half_rn(ob - __half2float(hb)));
                    *(__half2*)&g_qs1[base + d + 32] = __halves2half2(
                        __float2half_rn(pa - __half2float(hc)),
                        __float2half_rn(pb - __half2float(hd2)));
                }
            }
    } else {
#pragma unroll
        for (int mi = 0; mi < 2; mi++)
#pragma unroll
            for (int ni = 0; ni < 8; ni++) {
                const int d = 64 + 2 * (l & 3) + ni * 8;   // [64,128)
#pragma unroll
                for (int rr = 0; rr < 2; rr++) {
                    const int row = tq0 + mi * 16 + rr * 8;
                    const float oa = acc[mi][ni][rr * 2], ob = acc[mi][ni][rr * 2 + 1];
                    const size_t base = ((size_t)row * NH + h) * HD;
                    __half ha = __float2half_rn(oa), hb = __float2half_rn(ob);
                    *(__half2*)&g_qs0[base + d] = __halves2half2(ha, hb);
                    *(__half2*)&g_qs1[base + d] = __halves2half2(
                        __float2half_rn(oa - __half2float(ha)),
                        __float2half_rn(ob - __half2float(hb)));
                }
            }
    }
}

// ------------------- k = x @ wk_w: HMMA, pre-split operands (globals by name) ----------
// grid (20 m-tiles, 14 k-splits). 48 stages = 3 products x 16 chunks of 32. -> g_kpart
__global__ __launch_bounds__(256, 2) void k_mma()
{
    __shared__ __half sT[2][2][128 * LDT];

    const int bm = blockIdx.x;   // 0..19
    const int sp = blockIdx.y;   // 0..13
    const int tid = threadIdx.x, l = tid & 31, wid = tid >> 5;
    const int wm = wid & 3, wn = wid >> 2;

    const __half* xa[2] = {g_xs0, g_xs1};
    const __half* wb[2] = {g_wkT0, g_wkT1};

    float acc[2][8][4] = {};

    const uint32_t sbase = (uint32_t)__cvta_generic_to_shared(&sT[0][0][0]);
    const int r0 = (tid + 0) >> 2,   g0 = (tid + 0) & 3;
    const int r1 = (tid + 256) >> 2, g1 = (tid + 256) & 3;

    uint32_t aOff[2], bOff[4];
#pragma unroll
    for (int mi = 0; mi < 2; mi++)
        aOff[mi] = ((wm * 32 + mi * 16 + (l & 15)) * LDT + (l >> 4) * 8) * 2;
#pragma unroll
    for (int nj = 0; nj < 4; nj++)
        bOff[nj] = ((wn * 64 + nj * 16 + ((l >> 4) * 8) + (l & 7)) * LDT + ((l >> 3) & 1) * 8) * 2;

    const int kbase = sp * KCH;

    auto issue_stage = [&](int s, int buf) {
        const int p = s >> 4, kc = s & 15;
        const __half* asrc = xa[c_aidx[p]] + (size_t)bm * 128 * HID + kbase + kc * 32;
        const __half* bsrc = wb[c_bidx[p]] + kbase + kc * 32;
        const uint32_t ab = sbase + buf * 2 * TILE_B;
        const uint32_t bb = ab + TILE_B;
        cpa16(ab + (r0 * LDT + g0 * 8) * 2, asrc + (size_t)r0 * HID + g0 * 8);
        cpa16(ab + (r1 * LDT + g1 * 8) * 2, asrc + (size_t)r1 * HID + g1 * 8);
        cpa16(bb + (r0 * LDT + g0 * 8) * 2, bsrc + (size_t)r0 * HID + g0 * 8);
        cpa16(bb + (r1 * LDT + g1 * 8) * 2, bsrc + (size_t)r1 * HID + g1 * 8);
        CP_COMMIT();
    };

    issue_stage(0, 0);
#pragma unroll 1
    for (int s = 0; s < 48; s++) {
        const int buf = s & 1;
        CP_WAIT0();
        __syncthreads();
        if (s + 1 < 48) issue_stage(s + 1, buf ^ 1);
        const uint32_t ab = sbase + buf * 2 * TILE_B;
        const uint32_t bb = ab + TILE_B;
#pragma unroll
        for (int ks = 0; ks < 2; ks++) {
            uint32_t af[2][4], bf[4][4];
            ldsm4(af[0], ab + aOff[0] + ks * 32);
            ldsm4(af[1], ab + aOff[1] + ks * 32);
#pragma unroll
            for (int nj = 0; nj < 4; nj++) ldsm4(bf[nj], bb + bOff[nj] + ks * 32);
#pragma unroll
            for (int mi = 0; mi < 2; mi++)
#pragma unroll
                for (int ni = 0; ni < 8; ni++)
                    mma16816(acc[mi][ni], af[mi], &bf[ni >> 1][(ni & 1) * 2]);
        }
    }

    float* Cb = g_kpart + (size_t)sp * T_SEQ * HD + (size_t)bm * 128 * HD;
    const int rb = wm * 32 + (l >> 2);
    const int cb = wn * 64 + 2 * (l & 3);
#pragma unroll
    for (int mi = 0; mi < 2; mi++)
#pragma unroll
        for (int ni = 0; ni < 8; ni++) {
            const int row = rb + mi * 16, col = cb + ni * 8;
            *(float2*)&Cb[(size_t)row * HD + col]       = make_float2(acc[mi][ni][0], acc[mi][ni][1]);
            *(float2*)&Cb[(size_t)(row + 8) * HD + col] = make_float2(acc[mi][ni][2], acc[mi][ni][3]);
        }
}

// ------------------- fp16x2 split of full x (writes globals BY NAME) -------------------
__global__ void x_split(const float* __restrict__ x)
{
    const int i4 = blockIdx.x * blockDim.x + threadIdx.x;
    if (i4 >= T_SEQ * HID / 4) return;
    float4 v = ((const float4*)x)[i4];
    __half2 a0 = make_half2(__float2half_rn(v.x), __float2half_rn(v.y));
    __half2 a1 = make_half2(__float2half_rn(v.z), __float2half_rn(v.w));
    __half2 b0 = make_half2(__float2half_rn(v.x - __half2float(a0.x)),
                            __float2half_rn(v.y - __half2float(a0.y)));
    __half2 b1 = make_half2(__float2half_rn(v.z - __half2float(a1.x)),
                            __float2half_rn(v.w - __half2float(a1.y)));
    ((uint2*)g_xs0)[i4] = make_uint2(*(uint32_t*)&a0, *(uint32_t*)&a1);
    ((uint2*)g_xs1)[i4] = make_uint2(*(uint32_t*)&b0, *(uint32_t*)&b1);
}

// ------------------- transpose + split of wk_w [HID][HD] -> g_wkT [HD][HID] (by name) --
__global__ __launch_bounds__(256) void wk_tsplit(const float* __restrict__ wk)
{
    __shared__ float s[64][65];
    const int bx = blockIdx.x;  // n/64 over HD, 0..1
    const int by = blockIdx.y;  // k/64 over HID, 0..111
    const int tid = threadIdx.x;

#pragma unroll
    for (int i = 0; i < 4; i++) {
        int fid = tid + i * 256;
        int kr = fid >> 4;
        int nc = (fid & 15) * 4;
        float4 v = *(const float4*)(wk + (size_t)(by * 64 + kr) * HD + bx * 64 + nc);
        s[kr][nc] = v.x; s[kr][nc + 1] = v.y; s[kr][nc + 2] = v.z; s[kr][nc + 3] = v.w;
    }
    __syncthreads();

#pragma unroll
    for (int i = 0; i < 2; i++) {
        int task = tid + i * 256;
        int n = task >> 3, kg = task & 7;
        __align__(16) __half h0[8];
        __align__(16) __half h1[8];
#pragma unroll
        for (int j = 0; j < 8; j++) {
            float v = s[kg * 8 + j][n];
            __half a = __float2half_rn(v);
            h0[j] = a;
            h1[j] = __float2half_rn(v - __half2float(a));
        }
        size_t o = (size_t)(bx * 64 + n) * HID + by * 64 + kg * 8;
        *(uint4*)(g_wkT0 + o) = *(uint4*)h0;
        *(uint4*)(g_wkT1 + o) = *(uint4*)h1;
    }
}

// ------------------- split-K reduce + LayerNorm + RoPE + fp16x2 split for k -------------
__global__ __launch_bounds__(128) void k_postproc(
    const float* __restrict__ gamma, const float* __restrict__ beta,
    const float* __restrict__ fcos, const float* __restrict__ fsin)
{
    const int t = blockIdx.x;
    const int d = threadIdx.x;
    float v = 0.0f;
#pragma unroll
    for (int p = 0; p < KSPLIT; p++)
        v += g_kpart[(size_t)p * T_SEQ * HD + (size_t)t * HD + d];

    __shared__ float red[128];
    __shared__ float buf[128];
    red[d] = v; __syncthreads();
#pragma unroll
    for (int s = 64; s > 0; s >>= 1) { if (d < s) red[d] += red[d + s]; __syncthreads(); }
    const float mu = red[0] * (1.0f / 128.0f);
    __syncthreads();
    const float diff = v - mu;
    red[d] = diff * diff; __syncthreads();
#pragma unroll
    for (int s = 64; s > 0; s >>= 1) { if (d < s) red[d] += red[d + s]; __syncthreads(); }
    const float var = red[0] * (1.0f / 128.0f);
    const float inv = __frsqrt_rn(var + 1e-6f);
    const float nrm = diff * inv * gamma[d] + beta[d];
    buf[d] = nrm; __syncthreads();

    float outv;
    if (d < 32) {
        float c = fcos[t * 32 + d], s = fsin[t * 32 + d];
        outv = buf[d] * c - buf[d + 32] * s;
    } else if (d < 64) {
        float c = fcos[t * 32 + d - 32], s = fsin[t * 32 + d - 32];
        outv = buf[d - 32] * s + buf[d] * c;
    } else {
        outv = nrm;
    }
    __half h0 = __float2half_rn(outv);
    float r1 = outv - __half2float(h0);
    const size_t o = (size_t)t * HD + d;
    g_ks0[o] = h0; g_ks1[o] = __float2half_rn(r1);
}

// ------------------- fp16x2 split of qr active rows (float4 vectorized) ----------------
__global__ void qr_split(const float* __restrict__ qr)
{
    const int i4 = blockIdx.x * blockDim.x + threadIdx.x;
    if (i4 >= TQ * QLRD / 4) return;
    float4 v = ((const float4*)(qr + (size_t)TB * QLRD))[i4];
    __half2 a0 = make_half2(__float2half_rn(v.x), __float2half_rn(v.y));
    __half2 a1 = make_half2(__float2half_rn(v.z), __float2half_rn(v.w));
    __half2 b0 = make_half2(__float2half_rn(v.x - __half2float(a0.x)),
                            __float2half_rn(v.y - __half2float(a0.y)));
    __half2 b1 = make_half2(__float2half_rn(v.z - __half2float(a1.x)),
                            __float2half_rn(v.w - __half2float(a1.y)));
    ((uint2*)g_qrs0)[i4] = make_uint2(*(uint32_t*)&a0, *(uint32_t*)&a1);
    ((uint2*)g_qrs1)[i4] = make_uint2(*(uint32_t*)&b0, *(uint32_t*)&b1);
}

// ------------------- transpose + fp16x2 split of wq_b -> [NQ][QLRD] (proven, by name) ---
__global__ __launch_bounds__(256) void wq_tsplit(const float* __restrict__ wq_b)
{
    __shared__ float t[32][33];
    const int bx = blockIdx.x;  // n/32
    const int by = blockIdx.y;  // k/32
    const int tx = threadIdx.x & 31, ty = threadIdx.x >> 5;
#pragma unroll
    for (int i = 0; i < 4; i++) {
        int k = by * 32 + ty + i * 8;
        t[ty + i * 8][tx] = wq_b[(size_t)k * NQ + bx * 32 + tx];
    }
    __syncthreads();
#pragma unroll
    for (int i = 0; i < 4; i++) {
        int n = bx * 32 + ty + i * 8;
        float v = t[tx][ty + i * 8];
        __half h0 = __float2half_rn(v);
        float r1 = v - __half2float(h0);
        size_t o = (size_t)n * QLRD + by * 32 + tx;
        g_wqT0[o] = h0; g_wqT1[o] = __float2half_rn(r1);
    }
}

// ------------------- weights: split-K tiled SGEMM (proven R12) --------------------
__global__ __launch_bounds__(256) void w_gemm(const float* __restrict__ x,
                                              const float* __restrict__ wproj)
{
    __shared__ float As[8][132];
    __shared__ float Bs[8][68];

    const int bm = blockIdx.x;   // 0..3
    const int sp = blockIdx.y;   // 0..31
    const int tid = threadIdx.x;
    const int tx = tid & 15, ty = tid >> 4;
    const float* Ab = x + (size_t)(TB + bm * 128) * HID;

    const int arow = tid >> 1, aoff = (tid & 1) * 4;
    const int bkk = tid >> 4, bcol = (tid & 15) * 4;

    float acc[8][4];
#pragma unroll
    for (int i = 0; i < 8; i++)
#pragma unroll
        for (int j = 0; j < 4; j++) acc[i][j] = 0.0f;

    int k0 = sp * WKCH;
    const int kend = k0 + WKCH;
    for (; k0 < kend; k0 += 8) {
        float4 av = *(const float4*)(Ab + (size_t)arow * HID + k0 + aoff);
        float4 bv = make_float4(0.f, 0.f, 0.f, 0.f);
        if (tid < 128) bv = *(const float4*)(wproj + (size_t)(k0 + bkk) * NH + bcol);
        As[aoff + 0][arow] = av.x; As[aoff + 1][arow] = av.y;
        As[aoff + 2][arow] = av.z; As[aoff + 3][arow] = av.w;
        if (tid < 128) *(float4*)&Bs[bkk][bcol] = bv;
        __syncthreads();
#pragma unroll
        for (int kk = 0; kk < 8; kk++) {
            float a[8], b[4];
            *(float4*)&a[0] = *(const float4*)&As[kk][ty * 8];
            *(float4*)&a[4] = *(const float4*)&As[kk][ty * 8 + 4];
            *(float4*)&b[0] = *(const float4*)&Bs[kk][tx * 4];
#pragma unroll
            for (int i = 0; i < 8; i++)
#pragma unroll
                for (int j = 0; j < 4; j++)
                    acc[i][j] = fmaf(a[i], b[j], acc[i][j]);
        }
        __syncthreads();
    }

    float* Cb = g_wpart + (size_t)sp * TQ * NH + (size_t)bm * 128 * NH;
#pragma unroll
    for (int i = 0; i < 8; i++)
        *(float4*)&Cb[(size_t)(ty * 8 + i) * NH + tx * 4] =
            make_float4(acc[i][0], acc[i][1], acc[i][2], acc[i][3]);
}

__global__ void w_reduce()
{
    const int i = blockIdx.x * blockDim.x + threadIdx.x;
    if (i >= TQ * NH) return;
    float s = 0.0f;
#pragma unroll
    for (int p = 0; p < WSPLIT; p++)
        s += g_wpart[(size_t)p * TQ * NH + i];
    g_w[i] = (s * 0.125f) * 0.08838834764831843f;
}

// ------------------- fixed fill for rows t < 2048 -------------------
__global__ void fill_fixed(float* __restrict__ out)
{
    size_t i = (size_t)blockIdx.x * blockDim.x + threadIdx.x;
    const size_t total = (size_t)TB * T_SEQ / 4;
    if (i >= total) return;
    size_t s4 = (i % (T_SEQ / 4)) * 4;
    float v = (s4 < TB) ? 0.0f : NEGBIG;
    ((float4*)out)[i] = make_float4(v, v, v, v);
}

// ------------------- exact top-2048 via radix-256 select (4 passes) -------------------
__global__ __launch_bounds__(256) void topk_select(float* __restrict__ out)
{
    __shared__ unsigned keys[T_SEQ];
    __shared__ unsigned char flags[T_SEQ];
    __shared__ int whist[8][256];
    __shared__ int scan_s[256];
    __shared__ int bcast[2];
    __shared__ int rlt[8], req[8];
    __shared__ int cnts[256];

    const int tq = blockIdx.x;
    const int t = TB + tq;
    const int n = t + 1;
    const int tid = threadIdx.x;
    const int lane = tid & 31, wid = tid >> 5;
    const float* srow = g_score + (size_t)tq * T_SEQ;

    for (int i = tid; i < n; i += 256) {
        unsigned b = __float_as_uint(srow[i]);
        keys[i] = b ^ ((b & 0x80000000u) ? 0xFFFFFFFFu : 0x80000000u);
    }
    __syncthreads();

    const int m0 = tq + 1;
    int m = m0;
    unsigned prefix = 0;
#pragma unroll 1
    for (int pass = 0; pass < 4; pass++) {
        const int shift = 24 - pass * 8;
#pragma unroll
        for (int w = 0; w < 8; w++) whist[w][tid] = 0;
        __syncthreads();
        for (int i = tid; i < n; i += 256) {
            unsigned k = keys[i];
            bool ok = (pass == 0) || ((k >> (shift + 8)) == prefix);
            if (ok) atomicAdd(&whist[wid][(k >> shift) & 255], 1);
        }
        __syncthreads();
        int c = 0;
#pragma unroll
        for (int w = 0; w < 8; w++) c += whist[w][tid];
        scan_s[tid] = c;
        __syncthreads();
#pragma unroll
        for (int off = 1; off < 256; off <<= 1) {
            int v = (tid >= off) ? scan_s[tid - off] : 0;
            __syncthreads();
            scan_s[tid] += v;
            __syncthreads();
        }
        const int excl = scan_s[tid] - c;
        if (m > excl && m <= excl + c) { bcast[0] = tid; bcast[1] = m - excl; }
        __syncthreads();
        prefix = (prefix << 8) | (unsigned)bcast[0];
        m = bcast[1];
        __syncthreads();
    }
    const unsigned theta = prefix;

    int clt = 0, ceq = 0;
    for (int i = tid; i < n; i += 256) {
        unsigned k = keys[i];
        clt += (k < theta);
        ceq += (k == theta);
    }
#pragma unroll
    for (int o = 16; o; o >>= 1) {
        clt += __shfl_xor_sync(0xffffffffu, clt, o);
        ceq += __shfl_xor_sync(0xffffffffu, ceq, o);
    }
    if (lane == 0) { rlt[wid] = clt; req[wid] = ceq; }
    __syncthreads();
    int count_lt = 0, count_eq = 0;
#pragma unroll
    for (int w = 0; w < 8; w++) { count_lt += rlt[w]; count_eq += req[w]; }
    const int keep_eq = count_eq - (m0 - count_lt);

    const int chunk = (n + 255) / 256;
    const int beg = tid * chunk;
    const int end = (beg + chunk < n) ? (beg + chunk) : n;
    int local = 0;
    for (int i = beg; i < end; i++) local += (keys[i] == theta);
    cnts[tid] = local;
    __syncthreads();
    if (tid == 0) {
        int run = 0;
        for (int i = 0; i < 256; i++) { int c = cnts[i]; cnts[i] = run; run += c; }
    }
    __syncthreads();
    int rank = cnts[tid];
    for (int i = beg; i < end; i++)
        if (keys[i] == theta) { flags[i] = (rank < keep_eq) ? 1 : 0; rank++; }
    __syncthreads();

    float* orow = out + (size_t)t * T_SEQ;
    for (int s = tid; s < T_SEQ; s += 256) {
        float v = NEGBIG;
        if (s < n) {
            unsigned k = keys[s];
            if (k > theta || (k == theta && flags[s])) v = 0.0f;
        }
        orow[s] = v;
    }
}

// ------------------- launch -------------------
extern "C" void kernel_launch(void* const* d_in, const int* in_sizes, int n_in,
                              void* d_out, int out_size)
{
    (void)in_sizes; (void)n_in; (void)out_size;
    const float* x     = (const float*)d_in[0];
    const float* qr    = (const float*)d_in[1];
    const float* fcos  = (const float*)d_in[2];
    const float* fsin  = (const float*)d_in[3];
    const float* wq_b  = (const float*)d_in[5];
    const float* wk_w  = (const float*)d_in[6];
    const float* kgam  = (const float*)d_in[7];
    const float* kbet  = (const float*)d_in[8];
    const float* wproj = (const float*)d_in[9];
    float* out = (float*)d_out;

    x_split<<<(T_SEQ * HID / 4 + 255) / 256, 256>>>(x);
    wk_tsplit<<<dim3(HD / 64, HID / 64), 256>>>(wk_w);
    k_mma<<<dim3(20, KSPLIT), 256>>>();
    k_postproc<<<T_SEQ, 128>>>(kgam, kbet, fcos, fsin);
    w_gemm<<<dim3(4, WSPLIT), 256>>>(x, wproj);
    w_reduce<<<(TQ * NH + 255) / 256, 256>>>();
    qr_split<<<(TQ * QLRD / 4 + 255) / 256, 256>>>(qr);
    wq_tsplit<<<dim3(NQ / 32, QLRD / 32), 256>>>(wq_b);
    q_mma<<<dim3(NQ / 128, TQ / 128), 256>>>(fcos, fsin);
    score_mma<<<dim3(T_SEQ / 128, 256), 256>>>();
    fill_fixed<<<((TB * T_SEQ / 4) + 255) / 256, 256>>>(out);
    topk_select<<<TQ, 256>>>(out);
}

// round 15
// speedup vs baseline: 2.4604x; 1.1085x over previous
#include <cuda_runtime.h>
#include <cuda_fp16.h>
#include <stdint.h>

#define T_SEQ 2560
#define HID   7168
#define QLRD  1536
#define NH    64
#define HD    128
#define NQ    8192
#define TQ    512
#define TB    2048
#define KSPLIT 14
#define KCH   (HID / KSPLIT)    // 512
#define WSPLIT 32
#define WKCH (HID / WSPLIT)     // 224
#define NEGBIG (-1000000000.0f)

// ------------------- device scratch -------------------
__device__ __align__(16) float g_kpart[KSPLIT * T_SEQ * HD];
__device__ __align__(16) float g_wpart[WSPLIT * TQ * NH];
__device__ __align__(16) float g_w[TQ * NH];
__device__ __align__(16) float g_score[TQ * T_SEQ];
// fp16 2-way splits
__device__ __align__(16) __half g_qs0[TQ * NQ];
__device__ __align__(16) __half g_qs1[TQ * NQ];
__device__ __align__(16) __half g_ks0[T_SEQ * HD];
__device__ __align__(16) __half g_ks1[T_SEQ * HD];
__device__ __align__(16) __half g_qrs0[TQ * QLRD];
__device__ __align__(16) __half g_qrs1[TQ * QLRD];
__device__ __align__(16) __half g_wqT0[NQ * QLRD];
__device__ __align__(16) __half g_wqT1[NQ * QLRD];
__device__ __align__(16) __half g_wkT0[HD * HID];
__device__ __align__(16) __half g_wkT1[HD * HID];
__device__ __align__(16) __half g_xs0[T_SEQ * HID];
__device__ __align__(16) __half g_xs1[T_SEQ * HID];

// ------------------- mma.sync / cp.async helpers (baseline PTX) -------------------
__device__ __forceinline__ void ldsm4(uint32_t* r, uint32_t addr) {
    asm volatile("ldmatrix.sync.aligned.m8n8.x4.shared.b16 {%0,%1,%2,%3},[%4];"
        : "=r"(r[0]), "=r"(r[1]), "=r"(r[2]), "=r"(r[3]) : "r"(addr));
}
__device__ __forceinline__ void mma16816(float* d, const uint32_t* a, const uint32_t* b) {
    asm volatile("mma.sync.aligned.m16n8k16.row.col.f32.f16.f16.f32 "
        "{%0,%1,%2,%3},{%4,%5,%6,%7},{%8,%9},{%0,%1,%2,%3};"
        : "+f"(d[0]), "+f"(d[1]), "+f"(d[2]), "+f"(d[3])
        : "r"(a[0]), "r"(a[1]), "r"(a[2]), "r"(a[3]), "r"(b[0]), "r"(b[1]));
}
__device__ __forceinline__ void cpa16(uint32_t dst, const void* src) {
    asm volatile("cp.async.cg.shared.global [%0],[%1],16;" :: "r"(dst), "l"(src));
}
#define CP_COMMIT() asm volatile("cp.async.commit_group;" ::: "memory")
#define CP_WAIT0()  asm volatile("cp.async.wait_group 0;" ::: "memory")

__constant__ int c_aidx[3] = {0, 0, 1};
__constant__ int c_bidx[3] = {0, 1, 0};

#define LDT 40
#define TILE_B (128 * LDT * 2)

// ------------------- score: pipelined HMMA fp16 2-split/3-product + fused epilogue -----
__global__ __launch_bounds__(256, 2) void score_mma()
{
    __shared__ __half sT[2][2][128 * LDT];
    __shared__ float part[8][64];

    const int bs = blockIdx.x, bt = blockIdx.y;
    if (bs * 128 > TB + 2 * bt + 1) return;   // causal skip

    const int tid = threadIdx.x, l = tid & 31, wid = tid >> 5;
    const int wm = wid & 3, wn = wid >> 2;

    const __half* qa[2] = {g_qs0, g_qs1};
    const __half* kb[2] = {g_ks0, g_ks1};

    float acc[2][8][4] = {};

    const uint32_t sbase = (uint32_t)__cvta_generic_to_shared(&sT[0][0][0]);
    const int r0 = (tid + 0) >> 2,   g0 = (tid + 0) & 3;
    const int r1 = (tid + 256) >> 2, g1 = (tid + 256) & 3;

    uint32_t aOff[2], bOff[4];
#pragma unroll
    for (int mi = 0; mi < 2; mi++)
        aOff[mi] = ((wm * 32 + mi * 16 + (l & 15)) * LDT + (l >> 4) * 8) * 2;
#pragma unroll
    for (int nj = 0; nj < 4; nj++)
        bOff[nj] = ((wn * 64 + nj * 16 + ((l >> 4) * 8) + (l & 7)) * LDT + ((l >> 3) & 1) * 8) * 2;

    auto issue_stage = [&](int s, int buf) {
        const int p = s >> 2, kc = s & 3;
        const __half* asrc = qa[c_aidx[p]] + (size_t)bt * 128 * HD + kc * 32;
        const __half* bsrc = kb[c_bidx[p]] + (size_t)bs * 128 * HD + kc * 32;
        const uint32_t ab = sbase + buf * 2 * TILE_B;
        const uint32_t bb = ab + TILE_B;
        cpa16(ab + (r0 * LDT + g0 * 8) * 2, asrc + (size_t)r0 * HD + g0 * 8);
        cpa16(ab + (r1 * LDT + g1 * 8) * 2, asrc + (size_t)r1 * HD + g1 * 8);
        cpa16(bb + (r0 * LDT + g0 * 8) * 2, bsrc + (size_t)r0 * HD + g0 * 8);
        cpa16(bb + (r1 * LDT + g1 * 8) * 2, bsrc + (size_t)r1 * HD + g1 * 8);
        CP_COMMIT();
    };

    issue_stage(0, 0);
#pragma unroll 1
    for (int s = 0; s < 12; s++) {
        const int buf = s & 1;
        CP_WAIT0();
        __syncthreads();
        if (s + 1 < 12) issue_stage(s + 1, buf ^ 1);
        const uint32_t ab = sbase + buf * 2 * TILE_B;
        const uint32_t bb = ab + TILE_B;
#pragma unroll
        for (int ks = 0; ks < 2; ks++) {
            uint32_t af[2][4], bf[4][4];
            ldsm4(af[0], ab + aOff[0] + ks * 32);
            ldsm4(af[1], ab + aOff[1] + ks * 32);
#pragma unroll
            for (int nj = 0; nj < 4; nj++) ldsm4(bf[nj], bb + bOff[nj] + ks * 32);
#pragma unroll
            for (int mi = 0; mi < 2; mi++)
#pragma unroll
                for (int ni = 0; ni < 8; ni++)
                    mma16816(acc[mi][ni], af[mi], &bf[ni >> 1][(ni & 1) * 2]);
        }
    }

    const int rbase = wm * 32 + (l >> 2);
    const float w0 = g_w[bt * 128 + rbase];
    const float w1 = g_w[bt * 128 + rbase + 8];
    const float w2 = g_w[bt * 128 + rbase + 16];
    const float w3 = g_w[bt * 128 + rbase + 24];
#pragma unroll
    for (int ni = 0; ni < 8; ni++) {
        float s0 = fmaxf(acc[0][ni][0], 0.0f) * w0 + fmaxf(acc[0][ni][2], 0.0f) * w1
                 + fmaxf(acc[1][ni][0], 0.0f) * w2 + fmaxf(acc[1][ni][2], 0.0f) * w3;
        float s1 = fmaxf(acc[0][ni][1], 0.0f) * w0 + fmaxf(acc[0][ni][3], 0.0f) * w1
                 + fmaxf(acc[1][ni][1], 0.0f) * w2 + fmaxf(acc[1][ni][3], 0.0f) * w3;
#pragma unroll
        for (int o = 4; o < 32; o <<= 1) {
            s0 += __shfl_xor_sync(0xffffffffu, s0, o);
            s1 += __shfl_xor_sync(0xffffffffu, s1, o);
        }
        if (l < 4) {
            part[wid][ni * 8 + 2 * l] = s0;
            part[wid][ni * 8 + 2 * l + 1] = s1;
        }
    }
    __syncthreads();
    {
        const int col = tid & 127, tt = tid >> 7;
        const int wa = (col >> 6) * 4 + tt * 2;
        float s = part[wa][col & 63] + part[wa + 1][col & 63];
        g_score[(size_t)(bt * 2 + tt) * T_SEQ + bs * 128 + col] = s;
    }
}

// ------------------- q = qr @ wq_b: 128x128 HMMA, 144 stages, fused rope+split epilogue --
__global__ __launch_bounds__(256, 2) void q_mma(
    const float* __restrict__ fcos, const float* __restrict__ fsin)
{
    __shared__ __half sT[2][2][128 * LDT];

    const int bn = blockIdx.x, bm = blockIdx.y;
    const int tid = threadIdx.x, l = tid & 31, wid = tid >> 5;
    const int wm = wid & 3, wn = wid >> 2;

    const __half* qa[2] = {g_qrs0, g_qrs1};
    const __half* wb[2] = {g_wqT0, g_wqT1};

    float acc[2][8][4] = {};

    const uint32_t sbase = (uint32_t)__cvta_generic_to_shared(&sT[0][0][0]);
    const int r0 = (tid + 0) >> 2,   g0 = (tid + 0) & 3;
    const int r1 = (tid + 256) >> 2, g1 = (tid + 256) & 3;

    uint32_t aOff[2], bOff[4];
#pragma unroll
    for (int mi = 0; mi < 2; mi++)
        aOff[mi] = ((wm * 32 + mi * 16 + (l & 15)) * LDT + (l >> 4) * 8) * 2;
#pragma unroll
    for (int nj = 0; nj < 4; nj++)
        bOff[nj] = ((wn * 64 + nj * 16 + ((l >> 4) * 8) + (l & 7)) * LDT + ((l >> 3) & 1) * 8) * 2;

    auto issue_stage = [&](int s, int buf) {
        const int p = s / 48, kc = s % 48;
        const __half* asrc = qa[c_aidx[p]] + (size_t)bm * 128 * QLRD + kc * 32;
        const __half* bsrc = wb[c_bidx[p]] + (size_t)bn * 128 * QLRD + kc * 32;
        const uint32_t ab = sbase + buf * 2 * TILE_B;
        const uint32_t bb = ab + TILE_B;
        cpa16(ab + (r0 * LDT + g0 * 8) * 2, asrc + (size_t)r0 * QLRD + g0 * 8);
        cpa16(ab + (r1 * LDT + g1 * 8) * 2, asrc + (size_t)r1 * QLRD + g1 * 8);
        cpa16(bb + (r0 * LDT + g0 * 8) * 2, bsrc + (size_t)r0 * QLRD + g0 * 8);
        cpa16(bb + (r1 * LDT + g1 * 8) * 2, bsrc + (size_t)r1 * QLRD + g1 * 8);
        CP_COMMIT();
    };

    issue_stage(0, 0);
#pragma unroll 1
    for (int s = 0; s < 144; s++) {
        const int buf = s & 1;
        CP_WAIT0();
        __syncthreads();
        if (s + 1 < 144) issue_stage(s + 1, buf ^ 1);
        const uint32_t ab = sbase + buf * 2 * TILE_B;
        const uint32_t bb = ab + TILE_B;
#pragma unroll
        for (int ks = 0; ks < 2; ks++) {
            uint32_t af[2][4], bf[4][4];
            ldsm4(af[0], ab + aOff[0] + ks * 32);
            ldsm4(af[1], ab + aOff[1] + ks * 32);
#pragma unroll
            for (int nj = 0; nj < 4; nj++) ldsm4(bf[nj], bb + bOff[nj] + ks * 32);
#pragma unroll
            for (int mi = 0; mi < 2; mi++)
#pragma unroll
                for (int ni = 0; ni < 8; ni++)
                    mma16816(acc[mi][ni], af[mi], &bf[ni >> 1][(ni & 1) * 2]);
        }
    }

    // ---- fused epilogue: rope on dims [0,64) (wn==0), fp16x2 split, store g_qs ----
    const int tq0 = bm * 128 + wm * 32 + (l >> 2);
    const int h = bn;
    if (wn == 0) {
#pragma unroll
        for (int mi = 0; mi < 2; mi++)
#pragma unroll
            for (int ni = 0; ni < 4; ni++) {
                const int d = 2 * (l & 3) + ni * 8;        // even, < 32
#pragma unroll
                for (int rr = 0; rr < 2; rr++) {
                    const int row = tq0 + mi * 16 + rr * 8;
                    const int t = TB + row;
                    const float c0 = fcos[t * 32 + d],     s0 = fsin[t * 32 + d];
                    const float c1 = fcos[t * 32 + d + 1], s1 = fsin[t * 32 + d + 1];
                    const float x1a = acc[mi][ni][rr * 2],     x1b = acc[mi][ni][rr * 2 + 1];
                    const float x2a = acc[mi][ni + 4][rr * 2], x2b = acc[mi][ni + 4][rr * 2 + 1];
                    const float oa = x1a * c0 - x2a * s0, ob = x1b * c1 - x2b * s1;
                    const float pa = x1a * s0 + x2a * c0, pb = x1b * s1 + x2b * c1;
                    const size_t base = ((size_t)row * NH + h) * HD;
                    __half ha = __float2half_rn(oa), hb = __float2half_rn(ob);
                    __half hc = __float2half_rn(pa), hd2 = __float2half_rn(pb);
                    *(__half2*)&g_qs0[base + d]      = __halves2half2(ha, hb);
                    *(__half2*)&g_qs0[base + d + 32] = __halves2half2(hc, hd2);
                    *(__half2*)&g_qs1[base + d] = __halves2half2(
                        __float2half_rn(oa - __half2float(ha)),
                        __float2half_rn(ob - __half2float(hb)));
                    *(__half2*)&g_qs1[base + d + 32] = __halves2half2(
                        __float2half_rn(pa - __half2float(hc)),
                        __float2half_rn(pb - __half2float(hd2)));
                }
            }
    } else {
#pragma unroll
        for (int mi = 0; mi < 2; mi++)
#pragma unroll
            for (int ni = 0; ni < 8; ni++) {
                const int d = 64 + 2 * (l & 3) + ni * 8;   // [64,128)
#pragma unroll
                for (int rr = 0; rr < 2; rr++) {
                    const int row = tq0 + mi * 16 + rr * 8;
                    const float oa = acc[mi][ni][rr * 2], ob = acc[mi][ni][rr * 2 + 1];
                    const size_t base = ((size_t)row * NH + h) * HD;
                    __half ha = __float2half_rn(oa), hb = __float2half_rn(ob);
                    *(__half2*)&g_qs0[base + d] = __halves2half2(ha, hb);
                    *(__half2*)&g_qs1[base + d] = __halves2half2(
                        __float2half_rn(oa - __half2float(ha)),
                        __float2half_rn(ob - __half2float(hb)));
                }
            }
    }
}

// ------------------- k = x @ wk_w: HMMA, pre-split operands (globals by name) ----------
__global__ __launch_bounds__(256, 2) void k_mma()
{
    __shared__ __half sT[2][2][128 * LDT];

    const int bm = blockIdx.x;   // 0..19
    const int sp = blockIdx.y;   // 0..13
    const int tid = threadIdx.x, l = tid & 31, wid = tid >> 5;
    const int wm = wid & 3, wn = wid >> 2;

    const __half* xa[2] = {g_xs0, g_xs1};
    const __half* wb[2] = {g_wkT0, g_wkT1};

    float acc[2][8][4] = {};

    const uint32_t sbase = (uint32_t)__cvta_generic_to_shared(&sT[0][0][0]);
    const int r0 = (tid + 0) >> 2,   g0 = (tid + 0) & 3;
    const int r1 = (tid + 256) >> 2, g1 = (tid + 256) & 3;

    uint32_t aOff[2], bOff[4];
#pragma unroll
    for (int mi = 0; mi < 2; mi++)
        aOff[mi] = ((wm * 32 + mi * 16 + (l & 15)) * LDT + (l >> 4) * 8) * 2;
#pragma unroll
    for (int nj = 0; nj < 4; nj++)
        bOff[nj] = ((wn * 64 + nj * 16 + ((l >> 4) * 8) + (l & 7)) * LDT + ((l >> 3) & 1) * 8) * 2;

    const int kbase = sp * KCH;

    auto issue_stage = [&](int s, int buf) {
        const int p = s >> 4, kc = s & 15;
        const __half* asrc = xa[c_aidx[p]] + (size_t)bm * 128 * HID + kbase + kc * 32;
        const __half* bsrc = wb[c_bidx[p]] + kbase + kc * 32;
        const uint32_t ab = sbase + buf * 2 * TILE_B;
        const uint32_t bb = ab + TILE_B;
        cpa16(ab + (r0 * LDT + g0 * 8) * 2, asrc + (size_t)r0 * HID + g0 * 8);
        cpa16(ab + (r1 * LDT + g1 * 8) * 2, asrc + (size_t)r1 * HID + g1 * 8);
        cpa16(bb + (r0 * LDT + g0 * 8) * 2, bsrc + (size_t)r0 * HID + g0 * 8);
        cpa16(bb + (r1 * LDT + g1 * 8) * 2, bsrc + (size_t)r1 * HID + g1 * 8);
        CP_COMMIT();
    };

    issue_stage(0, 0);
#pragma unroll 1
    for (int s = 0; s < 48; s++) {
        const int buf = s & 1;
        CP_WAIT0();
        __syncthreads();
        if (s + 1 < 48) issue_stage(s + 1, buf ^ 1);
        const uint32_t ab = sbase + buf * 2 * TILE_B;
        const uint32_t bb = ab + TILE_B;
#pragma unroll
        for (int ks = 0; ks < 2; ks++) {
            uint32_t af[2][4], bf[4][4];
            ldsm4(af[0], ab + aOff[0] + ks * 32);
            ldsm4(af[1], ab + aOff[1] + ks * 32);
#pragma unroll
            for (int nj = 0; nj < 4; nj++) ldsm4(bf[nj], bb + bOff[nj] + ks * 32);
#pragma unroll
            for (int mi = 0; mi < 2; mi++)
#pragma unroll
                for (int ni = 0; ni < 8; ni++)
                    mma16816(acc[mi][ni], af[mi], &bf[ni >> 1][(ni & 1) * 2]);
        }
    }

    float* Cb = g_kpart + (size_t)sp * T_SEQ * HD + (size_t)bm * 128 * HD;
    const int rb = wm * 32 + (l >> 2);
    const int cb = wn * 64 + 2 * (l & 3);
#pragma unroll
    for (int mi = 0; mi < 2; mi++)
#pragma unroll
        for (int ni = 0; ni < 8; ni++) {
            const int row = rb + mi * 16, col = cb + ni * 8;
            *(float2*)&Cb[(size_t)row * HD + col]       = make_float2(acc[mi][ni][0], acc[mi][ni][1]);
            *(float2*)&Cb[(size_t)(row + 8) * HD + col] = make_float2(acc[mi][ni][2], acc[mi][ni][3]);
        }
}

// ------------------- fp16x2 split of full x (writes globals BY NAME) -------------------
__global__ void x_split(const float* __restrict__ x)
{
    const int i4 = blockIdx.x * blockDim.x + threadIdx.x;
    if (i4 >= T_SEQ * HID / 4) return;
    float4 v = ((const float4*)x)[i4];
    __half2 a0 = make_half2(__float2half_rn(v.x), __float2half_rn(v.y));
    __half2 a1 = make_half2(__float2half_rn(v.z), __float2half_rn(v.w));
    __half2 b0 = make_half2(__float2half_rn(v.x - __half2float(a0.x)),
                            __float2half_rn(v.y - __half2float(a0.y)));
    __half2 b1 = make_half2(__float2half_rn(v.z - __half2float(a1.x)),
                            __float2half_rn(v.w - __half2float(a1.y)));
    ((uint2*)g_xs0)[i4] = make_uint2(*(uint32_t*)&a0, *(uint32_t*)&a1);
    ((uint2*)g_xs1)[i4] = make_uint2(*(uint32_t*)&b0, *(uint32_t*)&b1);
}

// ------------------- transpose + split of wk_w [HID][HD] -> g_wkT [HD][HID] ------------
__global__ __launch_bounds__(256) void wk_tsplit(const float* __restrict__ wk)
{
    __shared__ float s[64][65];
    const int bx = blockIdx.x;
    const int by = blockIdx.y;
    const int tid = threadIdx.x;

#pragma unroll
    for (int i = 0; i < 4; i++) {
        int fid = tid + i * 256;
        int kr = fid >> 4;
        int nc = (fid & 15) * 4;
        float4 v = *(const float4*)(wk + (size_t)(by * 64 + kr) * HD + bx * 64 + nc);
        s[kr][nc] = v.x; s[kr][nc + 1] = v.y; s[kr][nc + 2] = v.z; s[kr][nc + 3] = v.w;
    }
    __syncthreads();

#pragma unroll
    for (int i = 0; i < 2; i++) {
        int task = tid + i * 256;
        int n = task >> 3, kg = task & 7;
        __align__(16) __half h0[8];
        __align__(16) __half h1[8];
#pragma unroll
        for (int j = 0; j < 8; j++) {
            float v = s[kg * 8 + j][n];
            __half a = __float2half_rn(v);
            h0[j] = a;
            h1[j] = __float2half_rn(v - __half2float(a));
        }
        size_t o = (size_t)(bx * 64 + n) * HID + by * 64 + kg * 8;
        *(uint4*)(g_wkT0 + o) = *(uint4*)h0;
        *(uint4*)(g_wkT1 + o) = *(uint4*)h1;
    }
}

// ------------------- split-K reduce + LayerNorm + RoPE + fp16x2 split for k -------------
__global__ __launch_bounds__(128) void k_postproc(
    const float* __restrict__ gamma, const float* __restrict__ beta,
    const float* __restrict__ fcos, const float* __restrict__ fsin)
{
    const int t = blockIdx.x;
    const int d = threadIdx.x;
    float v = 0.0f;
#pragma unroll
    for (int p = 0; p < KSPLIT; p++)
        v += g_kpart[(size_t)p * T_SEQ * HD + (size_t)t * HD + d];

    __shared__ float red[128];
    __shared__ float buf[128];
    red[d] = v; __syncthreads();
#pragma unroll
    for (int s = 64; s > 0; s >>= 1) { if (d < s) red[d] += red[d + s]; __syncthreads(); }
    const float mu = red[0] * (1.0f / 128.0f);
    __syncthreads();
    const float diff = v - mu;
    red[d] = diff * diff; __syncthreads();
#pragma unroll
    for (int s = 64; s > 0; s >>= 1) { if (d < s) red[d] += red[d + s]; __syncthreads(); }
    const float var = red[0] * (1.0f / 128.0f);
    const float inv = __frsqrt_rn(var + 1e-6f);
    const float nrm = diff * inv * gamma[d] + beta[d];
    buf[d] = nrm; __syncthreads();

    float outv;
    if (d < 32) {
        float c = fcos[t * 32 + d], s = fsin[t * 32 + d];
        outv = buf[d] * c - buf[d + 32] * s;
    } else if (d < 64) {
        float c = fcos[t * 32 + d - 32], s = fsin[t * 32 + d - 32];
        outv = buf[d - 32] * s + buf[d] * c;
    } else {
        outv = nrm;
    }
    __half h0 = __float2half_rn(outv);
    float r1 = outv - __half2float(h0);
    const size_t o = (size_t)t * HD + d;
    g_ks0[o] = h0; g_ks1[o] = __float2half_rn(r1);
}

// ------------------- fp16x2 split of qr active rows (float4 vectorized) ----------------
__global__ void qr_split(const float* __restrict__ qr)
{
    const int i4 = blockIdx.x * blockDim.x + threadIdx.x;
    if (i4 >= TQ * QLRD / 4) return;
    float4 v = ((const float4*)(qr + (size_t)TB * QLRD))[i4];
    __half2 a0 = make_half2(__float2half_rn(v.x), __float2half_rn(v.y));
    __half2 a1 = make_half2(__float2half_rn(v.z), __float2half_rn(v.w));
    __half2 b0 = make_half2(__float2half_rn(v.x - __half2float(a0.x)),
                            __float2half_rn(v.y - __half2float(a0.y)));
    __half2 b1 = make_half2(__float2half_rn(v.z - __half2float(a1.x)),
                            __float2half_rn(v.w - __half2float(a1.y)));
    ((uint2*)g_qrs0)[i4] = make_uint2(*(uint32_t*)&a0, *(uint32_t*)&a1);
    ((uint2*)g_qrs1)[i4] = make_uint2(*(uint32_t*)&b0, *(uint32_t*)&b1);
}

// ------------------- transpose + fp16x2 split of wq_b -> [NQ][QLRD] --------------------
__global__ __launch_bounds__(256) void wq_tsplit(const float* __restrict__ wq_b)
{
    __shared__ float t[32][33];
    const int bx = blockIdx.x;
    const int by = blockIdx.y;
    const int tx = threadIdx.x & 31, ty = threadIdx.x >> 5;
#pragma unroll
    for (int i = 0; i < 4; i++) {
        int k = by * 32 + ty + i * 8;
        t[ty + i * 8][tx] = wq_b[(size_t)k * NQ + bx * 32 + tx];
    }
    __syncthreads();
#pragma unroll
    for (int i = 0; i < 4; i++) {
        int n = bx * 32 + ty + i * 8;
        float v = t[tx][ty + i * 8];
        __half h0 = __float2half_rn(v);
        float r1 = v - __half2float(h0);
        size_t o = (size_t)n * QLRD + by * 32 + tx;
        g_wqT0[o] = h0; g_wqT1[o] = __float2half_rn(r1);
    }
}

// ------------------- weights: split-K tiled SGEMM (proven R12) --------------------
__global__ __launch_bounds__(256) void w_gemm(const float* __restrict__ x,
                                              const float* __restrict__ wproj)
{
    __shared__ float As[8][132];
    __shared__ float Bs[8][68];

    const int bm = blockIdx.x;
    const int sp = blockIdx.y;
    const int tid = threadIdx.x;
    const int tx = tid & 15, ty = tid >> 4;
    const float* Ab = x + (size_t)(TB + bm * 128) * HID;

    const int arow = tid >> 1, aoff = (tid & 1) * 4;
    const int bkk = tid >> 4, bcol = (tid & 15) * 4;

    float acc[8][4];
#pragma unroll
    for (int i = 0; i < 8; i++)
#pragma unroll
        for (int j = 0; j < 4; j++) acc[i][j] = 0.0f;

    int k0 = sp * WKCH;
    const int kend = k0 + WKCH;
    for (; k0 < kend; k0 += 8) {
        float4 av = *(const float4*)(Ab + (size_t)arow * HID + k0 + aoff);
        float4 bv = make_float4(0.f, 0.f, 0.f, 0.f);
        if (tid < 128) bv = *(const float4*)(wproj + (size_t)(k0 + bkk) * NH + bcol);
        As[aoff + 0][arow] = av.x; As[aoff + 1][arow] = av.y;
        As[aoff + 2][arow] = av.z; As[aoff + 3][arow] = av.w;
        if (tid < 128) *(float4*)&Bs[bkk][bcol] = bv;
        __syncthreads();
#pragma unroll
        for (int kk = 0; kk < 8; kk++) {
            float a[8], b[4];
            *(float4*)&a[0] = *(const float4*)&As[kk][ty * 8];
            *(float4*)&a[4] = *(const float4*)&As[kk][ty * 8 + 4];
            *(float4*)&b[0] = *(const float4*)&Bs[kk][tx * 4];
#pragma unroll
            for (int i = 0; i < 8; i++)
#pragma unroll
                for (int j = 0; j < 4; j++)
                    acc[i][j] = fmaf(a[i], b[j], acc[i][j]);
        }
        __syncthreads();
    }

    float* Cb = g_wpart + (size_t)sp * TQ * NH + (size_t)bm * 128 * NH;
#pragma unroll
    for (int i = 0; i < 8; i++)
        *(float4*)&Cb[(size_t)(ty * 8 + i) * NH + tx * 4] =
            make_float4(acc[i][0], acc[i][1], acc[i][2], acc[i][3]);
}

__global__ void w_reduce()
{
    const int i = blockIdx.x * blockDim.x + threadIdx.x;
    if (i >= TQ * NH) return;
    float s = 0.0f;
#pragma unroll
    for (int p = 0; p < WSPLIT; p++)
        s += g_wpart[(size_t)p * TQ * NH + i];
    g_w[i] = (s * 0.125f) * 0.08838834764831843f;
}

// ------------------- fixed fill for rows t < 2048 -------------------
__global__ void fill_fixed(float* __restrict__ out)
{
    size_t i = (size_t)blockIdx.x * blockDim.x + threadIdx.x;
    const size_t total = (size_t)TB * T_SEQ / 4;
    if (i >= total) return;
    size_t s4 = (i % (T_SEQ / 4)) * 4;
    float v = (s4 < TB) ? 0.0f : NEGBIG;
    ((float4*)out)[i] = make_float4(v, v, v, v);
}

// ------------------- exact top-2048 via radix-256 select (4 passes) -------------------
__global__ __launch_bounds__(256) void topk_select(float* __restrict__ out)
{
    __shared__ unsigned keys[T_SEQ];
    __shared__ unsigned char flags[T_SEQ];
    __shared__ int whist[8][256];
    __shared__ int scan_s[256];
    __shared__ int bcast[2];
    __shared__ int rlt[8], req[8];
    __shared__ int cnts[256];

    const int tq = blockIdx.x;
    const int t = TB + tq;
    const int n = t + 1;
    const int tid = threadIdx.x;
    const int lane = tid & 31, wid = tid >> 5;
    const float* srow = g_score + (size_t)tq * T_SEQ;

    for (int i = tid; i < n; i += 256) {
        unsigned b = __float_as_uint(srow[i]);
        keys[i] = b ^ ((b & 0x80000000u) ? 0xFFFFFFFFu : 0x80000000u);
    }
    __syncthreads();

    const int m0 = tq + 1;
    int m = m0;
    unsigned prefix = 0;
#pragma unroll 1
    for (int pass = 0; pass < 4; pass++) {
        const int shift = 24 - pass * 8;
#pragma unroll
        for (int w = 0; w < 8; w++) whist[w][tid] = 0;
        __syncthreads();
        for (int i = tid; i < n; i += 256) {
            unsigned k = keys[i];
            bool ok = (pass == 0) || ((k >> (shift + 8)) == prefix);
            if (ok) atomicAdd(&whist[wid][(k >> shift) & 255], 1);
        }
        __syncthreads();
        int c = 0;
#pragma unroll
        for (int w = 0; w < 8; w++) c += whist[w][tid];
        scan_s[tid] = c;
        __syncthreads();
#pragma unroll
        for (int off = 1; off < 256; off <<= 1) {
            int v = (tid >= off) ? scan_s[tid - off] : 0;
            __syncthreads();
            scan_s[tid] += v;
            __syncthreads();
        }
        const int excl = scan_s[tid] - c;
        if (m > excl && m <= excl + c) { bcast[0] = tid; bcast[1] = m - excl; }
        __syncthreads();
        prefix = (prefix << 8) | (unsigned)bcast[0];
        m = bcast[1];
        __syncthreads();
    }
    const unsigned theta = prefix;

    int clt = 0, ceq = 0;
    for (int i = tid; i < n; i += 256) {
        unsigned k = keys[i];
        clt += (k < theta);
        ceq += (k == theta);
    }
#pragma unroll
    for (int o = 16; o; o >>= 1) {
        clt += __shfl_xor_sync(0xffffffffu, clt, o);
        ceq += __shfl_xor_sync(0xffffffffu, ceq, o);
    }
    if (lane == 0) { rlt[wid] = clt; req[wid] = ceq; }
    __syncthreads();
    int count_lt = 0, count_eq = 0;
#pragma unroll
    for (int w = 0; w < 8; w++) { count_lt += rlt[w]; count_eq += req[w]; }
    const int keep_eq = count_eq - (m0 - count_lt);

    const int chunk = (n + 255) / 256;
    const int beg = tid * chunk;
    const int end = (beg + chunk < n) ? (beg + chunk) : n;
    int local = 0;
    for (int i = beg; i < end; i++) local += (keys[i] == theta);
    cnts[tid] = local;
    __syncthreads();
    if (tid == 0) {
        int run = 0;
        for (int i = 0; i < 256; i++) { int c = cnts[i]; cnts[i] = run; run += c; }
    }
    __syncthreads();
    int rank = cnts[tid];
    for (int i = beg; i < end; i++)
        if (keys[i] == theta) { flags[i] = (rank < keep_eq) ? 1 : 0; rank++; }
    __syncthreads();

    float* orow = out + (size_t)t * T_SEQ;
    for (int s = tid; s < T_SEQ; s += 256) {
        float v = NEGBIG;
        if (s < n) {
            unsigned k = keys[s];
            if (k > theta || (k == theta && flags[s])) v = 0.0f;
        }
        orow[s] = v;
    }
}

// ------------------- launch: fork/join two-branch graph -------------------
extern "C" void kernel_launch(void* const* d_in, const int* in_sizes, int n_in,
                              void* d_out, int out_size)
{
    (void)in_sizes; (void)n_in; (void)out_size;
    const float* x     = (const float*)d_in[0];
    const float* qr    = (const float*)d_in[1];
    const float* fcos  = (const float*)d_in[2];
    const float* fsin  = (const float*)d_in[3];
    const float* wq_b  = (const float*)d_in[5];
    const float* wk_w  = (const float*)d_in[6];
    const float* kgam  = (const float*)d_in[7];
    const float* kbet  = (const float*)d_in[8];
    const float* wproj = (const float*)d_in[9];
    float* out = (float*)d_out;

    static cudaStream_t s1 = nullptr;
    static cudaEvent_t evFork = nullptr, evJoin = nullptr;
    if (s1 == nullptr) {
        cudaStreamCreateWithFlags(&s1, cudaStreamNonBlocking);
        cudaEventCreateWithFlags(&evFork, cudaEventDisableTiming);
        cudaEventCreateWithFlags(&evJoin, cudaEventDisableTiming);
    }

    // fork: branch s1 handles k path + w path + fixed fill
    cudaEventRecord(evFork, 0);
    cudaStreamWaitEvent(s1, evFork, 0);

    // branch s1 (memory-heavy + k tensor work)
    x_split<<<(T_SEQ * HID / 4 + 255) / 256, 256, 0, s1>>>(x);
    wk_tsplit<<<dim3(HD / 64, HID / 64), 256, 0, s1>>>(wk_w);
    k_mma<<<dim3(20, KSPLIT), 256, 0, s1>>>();
    k_postproc<<<T_SEQ, 128, 0, s1>>>(kgam, kbet, fcos, fsin);
    w_gemm<<<dim3(4, WSPLIT), 256, 0, s1>>>(x, wproj);
    w_reduce<<<(TQ * NH + 255) / 256, 256, 0, s1>>>();
    fill_fixed<<<((TB * T_SEQ / 4) + 255) / 256, 256, 0, s1>>>(out);

    // main branch (critical path: q tensor work)
    qr_split<<<(TQ * QLRD / 4 + 255) / 256, 256>>>(qr);
    wq_tsplit<<<dim3(NQ / 32, QLRD / 32), 256>>>(wq_b);
    q_mma<<<dim3(NQ / 128, TQ / 128), 256>>>(fcos, fsin);

    // join, then score + topk
    cudaEventRecord(evJoin, s1);
    cudaStreamWaitEvent(0, evJoin, 0);
    score_mma<<<dim3(T_SEQ / 128, 256), 256>>>();
    topk_select<<<TQ, 256>>>(out);
}